// round 15
// baseline (speedup 1.0000x reference)
#include <cuda_runtime.h>
#include <cuda_fp16.h>
#include <math.h>
#include <stdint.h>

#define NHID   512
#define HEADS  8
#define BB     16
#define SS     511
#define LL     512
#define NNODE  8176
#define NTOK   8192
#define EE     131072
#define QKVD   1536
#define FFD    2048

// ----------------------------- scratch (device globals) --------------------
__device__ float g_h   [NTOK*NHID];
__device__ float g_x   [NTOK*NHID];
__device__ float g_xc  [NNODE*NHID];
__device__ float g_xg  [NNODE*NHID];
__device__ float g_ccat[HEADS*NHID];
__device__ float g_dcat[HEADS*64];
__device__ float g_tvec[2*NNODE];
__device__ float g_sin [2*NNODE];
__device__ float g_sout[2*NNODE];
__device__ float g_inv1[2*NNODE];
__device__ int   g_ind [2*NNODE];
__device__ int   g_outd[2*NNODE];
__device__ int   g_off [2*NNODE];
__device__ int   g_cur [2*NNODE];
__device__ int   g_csr [2*EE];
__device__ unsigned g_pm[(size_t)BB*HEADS*LL*(LL/32)];

// fp16 activations / weights
__device__ __half g_hh  [NTOK*NHID];
__device__ __half g_qkvh[NTOK*QKVD];
__device__ __half g_oh  [NTOK*NHID];
__device__ __half g_xh  [NTOK*NHID];
__device__ __half g_ffh [NTOK*FFD];
__device__ __half g_xfh [NNODE*NHID];
__device__ __half g_Ph  [2*NNODE*NHID];
__device__ __half g_Qh  [2*NNODE*NHID];
__device__ __half g_Th  [2*NNODE*NHID];
__device__ __half g_Mh  [HEADS*NHID*NHID];
__device__ __half g_Nch [HEADS*NHID*64];
__device__ __half g_xgh [NNODE*NHID];
__device__ __half g_fgh [NNODE*NHID];
__device__ __half g_qkvwh [4*NHID*QKVD];
__device__ __half g_attnwh[4*NHID*NHID];
__device__ __half g_ff1wh [4*NHID*FFD];
__device__ __half g_ff2wh [4*FFD*NHID];
__device__ __half g_s1wh  [HEADS*NHID*NHID];
__device__ __half g_s2wh  [HEADS*NHID*NHID];
__device__ __half g_gc3wh [HEADS*NHID*64];
__device__ __half g_gff1wh[NHID*NHID];
__device__ __half g_gff2wh[NHID*NHID];

__constant__ int c_pat[8] = {0,0,1,1,0,0,1,1};

// ----------------------------- helpers -------------------------------------
__device__ __forceinline__ unsigned h2u(float a, float b) {
    __half2 h = __floats2half2_rn(a, b);
    return *reinterpret_cast<unsigned*>(&h);
}
__device__ __forceinline__ uint2 f4h(float4 v) {
    uint2 r; r.x = h2u(v.x, v.y); r.y = h2u(v.z, v.w); return r;
}
__device__ __forceinline__ void addh8(float* a, uint4 u, float s) {
    __half2* hp = (__half2*)&u;
    #pragma unroll
    for (int i = 0; i < 4; i++) {
        float2 f = __half22float2(hp[i]);
        a[2*i]   += f.x * s;
        a[2*i+1] += f.y * s;
    }
}
__device__ __forceinline__ uint4 pack8(const float* a, float s) {
    return make_uint4(h2u(a[0]*s, a[1]*s), h2u(a[2]*s, a[3]*s),
                      h2u(a[4]*s, a[5]*s), h2u(a[6]*s, a[7]*s));
}
__device__ __forceinline__ void ldsm4(unsigned &d0, unsigned &d1, unsigned &d2, unsigned &d3,
                                      unsigned addr) {
    asm volatile("ldmatrix.sync.aligned.m8n8.x4.shared.b16 {%0,%1,%2,%3}, [%4];"
                 : "=r"(d0), "=r"(d1), "=r"(d2), "=r"(d3) : "r"(addr));
}
__device__ __forceinline__ void ldsm4t(unsigned &d0, unsigned &d1, unsigned &d2, unsigned &d3,
                                       unsigned addr) {
    asm volatile("ldmatrix.sync.aligned.m8n8.x4.trans.shared.b16 {%0,%1,%2,%3}, [%4];"
                 : "=r"(d0), "=r"(d1), "=r"(d2), "=r"(d3) : "r"(addr));
}
__device__ __forceinline__ void ldsm2(unsigned &d0, unsigned &d1, unsigned addr) {
    asm volatile("ldmatrix.sync.aligned.m8n8.x2.shared.b16 {%0,%1}, [%2];"
                 : "=r"(d0), "=r"(d1) : "r"(addr));
}
__device__ __forceinline__ void ldsm2t(unsigned &d0, unsigned &d1, unsigned addr) {
    asm volatile("ldmatrix.sync.aligned.m8n8.x2.trans.shared.b16 {%0,%1}, [%2];"
                 : "=r"(d0), "=r"(d1) : "r"(addr));
}
__device__ __forceinline__ void mma16(float* c, const unsigned* a, const unsigned* b) {
    asm volatile(
        "mma.sync.aligned.m16n8k16.row.col.f32.f16.f16.f32 "
        "{%0,%1,%2,%3}, {%4,%5,%6,%7}, {%8,%9}, {%0,%1,%2,%3};"
        : "+f"(c[0]), "+f"(c[1]), "+f"(c[2]), "+f"(c[3])
        : "r"(a[0]), "r"(a[1]), "r"(a[2]), "r"(a[3]), "r"(b[0]), "r"(b[1]));
}
__device__ __forceinline__ void cpa16(unsigned d, const void* s, bool v) {
    asm volatile("cp.async.cg.shared.global [%0], [%1], 16, %2;"
                 :: "r"(d), "l"(s), "r"(v ? 16u : 0u));
}
#define CP_COMMIT asm volatile("cp.async.commit_group;" ::: "memory")
#define CP_WAIT1  asm volatile("cp.async.wait_group 1;" ::: "memory")
#define CP_WAIT0  asm volatile("cp.async.wait_group 0;" ::: "memory")

// ----------------------------- GEMM param block -----------------------------
struct GPH {
    const __half *A, *B;
    const float *bias, *res;
    float *C; __half *Ch;
    const float *sinp, *tvp, *dcp, *g3bp;   // xcepi fusion (hmode)
    int xcepi;
    int lda, ldb, ldc, ldres;
    int M, N, K;
    float resScale;
    int relu;
    int zDiv, hmode;
    int gx, gy, tiles;
    long long aO, aI, bO, bI, cO, cI, rO, rI, biasO;
};
struct GP {
    const float *A, *B, *bias;
    float *C;
    int ldb, N, K;
    long long aO, bO, cO, biasO;
};

// ----------------------------- fp16 cp.async GEMM (persistent, K-slice 64) -
// 256 thr, tile 128 x BN, 8 warps, K-slice 64 halves, 3 cp.async stages.
template<int BN>
__global__ __launch_bounds__(256, 2) void mma_k(GPH p) {
    constexpr int WGN  = (BN == 128) ? 4 : 2;
    constexpr int WGM  = 8 / WGN;
    constexpr int WM   = 128 / WGM;
    constexpr int WN   = BN / WGN;
    constexpr int MF   = WM / 16;
    constexpr int NF   = WN / 8;
    constexpr int ASTH = 72;                 // A row stride halves (64 + 8 pad)
    constexpr int BSTH = BN + 8;             // B row stride halves
    constexpr int AW   = 128 * ASTH / 2;     // words per A stage
    constexpr int BW   = 64 * BSTH / 2;      // words per B stage (64 k-rows)

    extern __shared__ unsigned smw[];
    unsigned sb = (unsigned)__cvta_generic_to_shared(smw);
    unsigned aBase[3], bBase[3];
    #pragma unroll
    for (int s = 0; s < 3; s++) {
        aBase[s] = sb + (unsigned)(s * AW) * 4u;
        bBase[s] = sb + (unsigned)(3 * AW + s * BW) * 4u;
    }

    int tid = threadIdx.x, lane = tid & 31, warp = tid >> 5;
    int wm = warp / WGN, wn = warp % WGN;
    int ar = tid >> 1, ac0 = (tid & 1) * 32;            // A fill: row, 32-half block
    int br = tid >> 2;                                  // B fill: k-row 0..63
    int bc0 = (BN == 128) ? (tid & 3) * 32 : (tid & 3) * 16;
    int aRow = (lane & 7) + ((lane >> 3) & 1) * 8;
    unsigned aKoff = ((lane >> 4) & 1) * 16;
    int bRowT = (lane & 7) + ((lane >> 3) & 1) * 8;
    int bColT = ((lane >> 4) & 1) * 8;

    for (int t = blockIdx.x; t < p.tiles; t += gridDim.x) {
        int bx = t % p.gx; int rr = t / p.gx;
        int by = rr % p.gy; int bz = rr / p.gy;

        __syncthreads();

        const __half *A, *B;
        float *C = nullptr; __half *Ch = nullptr;
        const float *bias = nullptr, *res = nullptr;
        if (p.hmode) {
            A = p.A + (((bz >> 1) & 1) ? p.aI : 0);
            B = p.B + (size_t)bz * p.bO;
            if (p.C)  C  = p.C  + (size_t)bz * p.cO;
            if (p.Ch) Ch = p.Ch + (size_t)bz * p.cO;
        } else {
            int zo = bz / p.zDiv, zi = bz % p.zDiv;
            A = p.A + zo * p.aO + zi * p.aI;
            B = p.B + zo * p.bO + zi * p.bI;
            if (p.C)  C  = p.C  + zo * p.cO + zi * p.cI;
            if (p.Ch) Ch = p.Ch + zo * p.cO + zi * p.cI;
            if (p.bias) bias = p.bias + zo * p.biasO;
            if (p.res)  res  = p.res + zo * p.rO + zi * p.rI;
        }
        int m0 = bx * 128, n0 = by * BN;
        bool av = (m0 + ar) < p.M;

        auto issue = [&](int s, int k0) {
            const __half* asrc = A + (size_t)(m0 + ar) * p.lda + k0 + ac0;
            unsigned adst = aBase[s] + (unsigned)(ar * ASTH + ac0) * 2u;
            #pragma unroll
            for (int i = 0; i < 4; i++)
                cpa16(adst + i * 16u, asrc + i * 8, av);
            const __half* bsrc = B + (size_t)(k0 + br) * p.ldb + n0 + bc0;
            unsigned bdst = bBase[s] + (unsigned)(br * BSTH + bc0) * 2u;
            #pragma unroll
            for (int i = 0; i < (BN == 128 ? 4 : 2); i++)
                cpa16(bdst + i * 16u, bsrc + i * 8, true);
        };

        float acc[MF][NF][4];
        #pragma unroll
        for (int f = 0; f < MF; f++)
            #pragma unroll
            for (int j = 0; j < NF; j++)
                #pragma unroll
                for (int q = 0; q < 4; q++) acc[f][j][q] = 0.f;

        int nIter = p.K >> 6;
        issue(0, 0);  CP_COMMIT;
        issue(1, 64); CP_COMMIT;

        for (int i = 0; i < nIter; i++) {
            CP_WAIT1;
            __syncthreads();
            if (i + 2 < nIter) issue((i + 2) % 3, (i + 2) * 64);
            CP_COMMIT;

            int s = i % 3;
            unsigned aB = aBase[s], bB = bBase[s];
            #pragma unroll
            for (int kk = 0; kk < 64; kk += 16) {
                unsigned bfr[NF][2];
                #pragma unroll
                for (int j = 0; j < NF; j += 2) {
                    unsigned addr = bB + (unsigned)((kk + bRowT) * BSTH
                                  + wn * WN + j * 8 + bColT) * 2u;
                    ldsm4t(bfr[j][0], bfr[j][1], bfr[j+1][0], bfr[j+1][1], addr);
                }
                #pragma unroll
                for (int f = 0; f < MF; f++) {
                    int row = wm * WM + f * 16 + aRow;
                    unsigned addr = aB + (unsigned)(row * ASTH + kk) * 2u + aKoff;
                    unsigned afr[4];
                    ldsm4(afr[0], afr[1], afr[2], afr[3], addr);
                    #pragma unroll
                    for (int j = 0; j < NF; j++) mma16(acc[f][j], afr, bfr[j]);
                }
            }
        }

        // xcepi fusion pointers (hmode)
        const float *sinp = nullptr, *tvp = nullptr, *dcp = nullptr, *g3p = nullptr;
        if (p.xcepi) {
            int g = (bz >> 1) & 1;
            sinp = p.sinp + g * NNODE;
            tvp  = p.tvp  + g * NNODE;
            dcp  = p.dcp  + bz * 64;
            g3p  = p.g3bp + bz * 64;
        }

        #pragma unroll
        for (int f = 0; f < MF; f++) {
            int r0 = m0 + wm * WM + f * 16 + (lane >> 2);
            int r1 = r0 + 8;
            #pragma unroll
            for (int j = 0; j < NF; j++) {
                int col = n0 + wn * WN + j * 8 + 2 * (lane & 3);
                float b0 = 0.f, b1 = 0.f;
                if (bias) { b0 = bias[col]; b1 = bias[col + 1]; }
                float v0 = acc[f][j][0] + b0, v1 = acc[f][j][1] + b1;
                float v2 = acc[f][j][2] + b0, v3 = acc[f][j][3] + b1;
                if (p.relu) {
                    v0 = fmaxf(v0, 0.f); v1 = fmaxf(v1, 0.f);
                    v2 = fmaxf(v2, 0.f); v3 = fmaxf(v3, 0.f);
                }
                if (r0 < p.M) {
                    if (res) {
                        v0 += p.resScale * res[(size_t)r0 * p.ldres + col];
                        v1 += p.resScale * res[(size_t)r0 * p.ldres + col + 1];
                    }
                    if (p.xcepi) {
                        float si = sinp[r0], tv = tvp[r0];
                        v0 = si * v0 + si * tv * dcp[col]     + g3p[col];
                        v1 = si * v1 + si * tv * dcp[col + 1] + g3p[col + 1];
                    }
                    if (C)  *(float2*)&C[(size_t)r0 * p.ldc + col] = make_float2(v0, v1);
                    if (Ch) *(unsigned*)&Ch[(size_t)r0 * p.ldc + col] = h2u(v0, v1);
                }
                if (r1 < p.M) {
                    if (res) {
                        v2 += p.resScale * res[(size_t)r1 * p.ldres + col];
                        v3 += p.resScale * res[(size_t)r1 * p.ldres + col + 1];
                    }
                    if (p.xcepi) {
                        float si = sinp[r1], tv = tvp[r1];
                        v2 = si * v2 + si * tv * dcp[col]     + g3p[col];
                        v3 = si * v3 + si * tv * dcp[col + 1] + g3p[col + 1];
                    }
                    if (C)  *(float2*)&C[(size_t)r1 * p.ldc + col] = make_float2(v2, v3);
                    if (Ch) *(unsigned*)&Ch[(size_t)r1 * p.ldc + col] = h2u(v2, v3);
                }
            }
        }
    }
}

#define MMA_SMEM(BN) ((3 * (128*72/2) + 3 * (64*((BN)+8)/2)) * 4)
#define PERSIST_CTAS 296

static void mgemm(const __half* A, int lda, const __half* B, int ldb,
                  float* C, __half* Ch, int ldc,
                  int M, int N, int K,
                  const float* bias = nullptr, const float* res = nullptr, int ldres = 0,
                  float resScale = 0.f, int relu = 0,
                  int z = 1, int zDiv = 1,
                  long long aO=0, long long aI=0, long long bO=0, long long bI=0,
                  long long cO=0, long long cI=0, long long rO=0, long long rI=0,
                  long long biasO=0, int hmode = 0,
                  const float* sinp = nullptr, const float* tvp = nullptr,
                  const float* dcp = nullptr, const float* g3bp = nullptr) {
    GPH p;
    p.A=A; p.B=B; p.bias=bias; p.res=res; p.C=C; p.Ch=Ch;
    p.sinp=sinp; p.tvp=tvp; p.dcp=dcp; p.g3bp=g3bp; p.xcepi = (sinp != nullptr);
    p.lda=lda; p.ldb=ldb; p.ldc=ldc; p.ldres=ldres;
    p.M=M; p.N=N; p.K=K; p.resScale=resScale; p.relu=relu; p.zDiv=zDiv; p.hmode=hmode;
    p.aO=aO; p.aI=aI; p.bO=bO; p.bI=bI; p.cO=cO; p.cI=cI; p.rO=rO; p.rI=rI; p.biasO=biasO;
    p.gx = (M + 127) / 128;
    if (N % 128 == 0) {
        p.gy = N / 128;
        p.tiles = p.gx * p.gy * z;
        int ctas = p.tiles < PERSIST_CTAS ? p.tiles : PERSIST_CTAS;
        mma_k<128><<<ctas, 256, MMA_SMEM(128)>>>(p);
    } else {
        p.gy = N / 64;
        p.tiles = p.gx * p.gy * z;
        int ctas = p.tiles < PERSIST_CTAS ? p.tiles : PERSIST_CTAS;
        mma_k<64><<<ctas, 256, MMA_SMEM(64)>>>(p);
    }
}

// ----------------------------- fused weight f32->f16 (9 segments) ----------
struct TOH9 {
    const float* s[9];
    __half* d[9];
    int off[10];
};
__global__ void k_tohalf_all(TOH9 t) {
    int g = blockIdx.x * blockDim.x + threadIdx.x;
    if (g >= t.off[9]) return;
    int seg = 0;
    #pragma unroll
    for (int i = 1; i < 9; i++) seg += (g >= t.off[i]);
    int loc = (g - t.off[seg]) * 8;
    const float* in = t.s[seg] + loc;
    __half* out = t.d[seg] + loc;
    uint2 a = f4h(*(const float4*)(in));
    uint2 b = f4h(*(const float4*)(in + 4));
    *(uint4*)(out) = make_uint4(a.x, a.y, b.x, b.y);
}

// ----------------------------- flash attention (fp16, cp.async) ------------
#define KSTW 36
#define FLASH_SMEM ((4*64*KSTW + 128*KSTW) * 4)

__global__ __launch_bounds__(256, 2) void k_flash() {
    extern __shared__ unsigned sm[];
    unsigned sb = (unsigned)__cvta_generic_to_shared(sm);
    unsigned kOff[2] = { sb, sb + 4608u*4u };
    unsigned vOff[2] = { sb + 2304u*4u, sb + 6912u*4u };
    unsigned* sP = sm + 9216;
    unsigned sPb = sb + 9216u*4u;

    int tid = threadIdx.x, lane = tid & 31, w = tid >> 5;
    int m0 = blockIdx.x * 128;
    int bh = blockIdx.y; int h = bh & 7, b = bh >> 3;
    const __half* qb = g_qkvh + (size_t)(b * LL) * QKVD + h * 192;

    int l15 = lane & 15;
    int aRow = (lane & 7) + ((lane >> 3) & 1) * 8;
    unsigned aKoff = ((lane >> 4) & 1) * 16;
    int arow = 16*w + aRow;

    int key = tid >> 2, kc4 = tid & 3;
    auto issue = [&](int st, int kt) {
        const __half* kp = qb + (size_t)(kt*64 + key) * QKVD + 64;
        unsigned kd = kOff[st] + (unsigned)key * 144u;
        cpa16(kd + kc4*16,      kp + kc4*8,       true);
        cpa16(kd + (kc4+4)*16,  kp + (kc4+4)*8,   true);
        unsigned vd = vOff[st] + (unsigned)key * 144u;
        cpa16(vd + kc4*16,      kp + 64 + kc4*8,  true);
        cpa16(vd + (kc4+4)*16,  kp + 64 + (kc4+4)*8, true);
    };

    issue(0, 0); CP_COMMIT;

    {
        int row = tid >> 1, dh = (tid & 1) * 32;
        const uint4* src = (const uint4*)(qb + (size_t)(m0 + row) * QKVD + dh);
        unsigned* dst = sP + row * KSTW + dh/2;
        #pragma unroll
        for (int c = 0; c < 4; c++) *(uint4*)(dst + c*4) = src[c];
    }
    __syncthreads();
    unsigned qf[4][4];
    #pragma unroll
    for (int kc = 0; kc < 4; kc++)
        ldsm4(qf[kc][0], qf[kc][1], qf[kc][2], qf[kc][3],
              sPb + (unsigned)(arow * KSTW) * 4u + (unsigned)kc * 32u + aKoff);

    float accO[8][4];
    #pragma unroll
    for (int j = 0; j < 8; j++)
        #pragma unroll
        for (int q = 0; q < 4; q++) accO[j][q] = 0.f;
    float m0r = -INFINITY, m1r = -INFINITY, l0r = 0.f, l1r = 0.f;

    const unsigned* pmr0 = g_pm + ((size_t)bh * LL + m0 + 16*w + (lane >> 2)) * 16;
    const unsigned* pmr1 = pmr0 + 8 * 16;

    for (int kt = 0; kt < 8; kt++) {
        CP_WAIT0;
        __syncthreads();
        if (kt + 1 < 8) { issue((kt + 1) & 1, kt + 1); CP_COMMIT; }
        int st = kt & 1;

        float S[8][4];
        #pragma unroll
        for (int nt = 0; nt < 8; nt++)
            #pragma unroll
            for (int q = 0; q < 4; q++) S[nt][q] = 0.f;
        #pragma unroll
        for (int kc = 0; kc < 4; kc++) {
            #pragma unroll
            for (int nt = 0; nt < 8; nt++) {
                unsigned bb[2];
                unsigned addr = kOff[st] + (unsigned)((nt*8 + (l15 & 7)) * KSTW) * 4u
                                        + (unsigned)kc * 32u + (unsigned)(l15 >> 3) * 16u;
                ldsm2(bb[0], bb[1], addr);
                mma16(S[nt], qf[kc], bb);
            }
        }

        uint2 mw0 = *(const uint2*)(pmr0 + kt*2);
        uint2 mw1 = *(const uint2*)(pmr1 + kt*2);
        unsigned q0[2] = {mw0.x, mw0.y};
        unsigned q1[2] = {mw1.x, mw1.y};
        float rm0 = -INFINITY, rm1 = -INFINITY;
        #pragma unroll
        for (int nt = 0; nt < 8; nt++) {
            int j0 = nt*8 + 2*(lane & 3), j1 = j0 + 1;
            S[nt][0] = ((q0[j0>>5] >> (j0&31)) & 1u) ? S[nt][0]*0.125f : -INFINITY;
            S[nt][1] = ((q0[j1>>5] >> (j1&31)) & 1u) ? S[nt][1]*0.125f : -INFINITY;
            S[nt][2] = ((q1[j0>>5] >> (j0&31)) & 1u) ? S[nt][2]*0.125f : -INFINITY;
            S[nt][3] = ((q1[j1>>5] >> (j1&31)) & 1u) ? S[nt][3]*0.125f : -INFINITY;
            rm0 = fmaxf(rm0, fmaxf(S[nt][0], S[nt][1]));
            rm1 = fmaxf(rm1, fmaxf(S[nt][2], S[nt][3]));
        }
        rm0 = fmaxf(rm0, __shfl_xor_sync(0xffffffffu, rm0, 1));
        rm0 = fmaxf(rm0, __shfl_xor_sync(0xffffffffu, rm0, 2));
        rm1 = fmaxf(rm1, __shfl_xor_sync(0xffffffffu, rm1, 1));
        rm1 = fmaxf(rm1, __shfl_xor_sync(0xffffffffu, rm1, 2));

        float mn0 = fmaxf(m0r, rm0), mn1 = fmaxf(m1r, rm1);
        float a0 = __expf(m0r - mn0), a1 = __expf(m1r - mn1);
        m0r = mn0; m1r = mn1;

        int prow0 = 16*w + (lane >> 2), prow1 = prow0 + 8;
        float rs0 = 0.f, rs1 = 0.f;
        #pragma unroll
        for (int nt = 0; nt < 8; nt++) {
            int jw = nt*4 + (lane & 3);
            float p00 = __expf(S[nt][0] - mn0), p01 = __expf(S[nt][1] - mn0);
            float p10 = __expf(S[nt][2] - mn1), p11 = __expf(S[nt][3] - mn1);
            rs0 += p00 + p01; rs1 += p10 + p11;
            sP[prow0*KSTW + jw] = h2u(p00, p01);
            sP[prow1*KSTW + jw] = h2u(p10, p11);
        }
        rs0 += __shfl_xor_sync(0xffffffffu, rs0, 1);
        rs0 += __shfl_xor_sync(0xffffffffu, rs0, 2);
        rs1 += __shfl_xor_sync(0xffffffffu, rs1, 1);
        rs1 += __shfl_xor_sync(0xffffffffu, rs1, 2);
        l0r = l0r * a0 + rs0;
        l1r = l1r * a1 + rs1;

        #pragma unroll
        for (int j = 0; j < 8; j++) {
            accO[j][0] *= a0; accO[j][1] *= a0;
            accO[j][2] *= a1; accO[j][3] *= a1;
        }
        __syncwarp();

        #pragma unroll
        for (int kc = 0; kc < 4; kc++) {
            unsigned pf[4];
            ldsm4(pf[0], pf[1], pf[2], pf[3],
                  sPb + (unsigned)(arow * KSTW) * 4u + (unsigned)kc * 32u + aKoff);
            #pragma unroll
            for (int nt = 0; nt < 8; nt++) {
                unsigned bb[2];
                unsigned addr = vOff[st] + (unsigned)((kc*16 + (l15 & 7) + (l15 >> 3)*8) * KSTW) * 4u
                                        + (unsigned)nt * 16u;
                ldsm2t(bb[0], bb[1], addr);
                mma16(accO[nt], pf, bb);
            }
        }
    }

    float inv0 = 1.f / l0r, inv1 = 1.f / l1r;
    int r0 = m0 + 16*w + (lane >> 2), r1 = r0 + 8;
    __half* o0 = g_oh + (size_t)(b*LL + r0) * NHID + h*64;
    __half* o1 = g_oh + (size_t)(b*LL + r1) * NHID + h*64;
    #pragma unroll
    for (int nt = 0; nt < 8; nt++) {
        int col = nt*8 + 2*(lane & 3);
        *(unsigned*)&o0[col] = h2u(accO[nt][0]*inv0, accO[nt][1]*inv0);
        *(unsigned*)&o1[col] = h2u(accO[nt][2]*inv1, accO[nt][3]*inv1);
    }
}

// pack mask (int32 bool, layout [b][i][h][j]) -> bits [b][h][i][j/32]
__global__ void k_packmask(const int* __restrict__ mask) {
    int row = blockIdx.x * 8 + (threadIdx.x >> 5);
    int lane = threadIdx.x & 31;
    const int* mr = mask + (size_t)row * LL;
    int b_i = row >> 3, h = row & 7;
    int b = b_i >> 9, i = b_i & 511;
    unsigned* out = g_pm + (((size_t)(b*HEADS + h) * LL + i) << 4);
    #pragma unroll
    for (int wd = 0; wd < 16; wd++) {
        unsigned bits = __ballot_sync(0xffffffffu, mr[wd*32 + lane] != 0);
        if (lane == 0) out[wd] = bits;
    }
}

// ----------------------------- small FFMA GEMM (M=1) -----------------------
__global__ void gemm1_k(GP p) {
    int zo = blockIdx.z;
    const float* A = p.A + zo * p.aO;
    const float* B = p.B + zo * p.bO;
    float* C = p.C + zo * p.cO;
    const float* bias = p.bias ? p.bias + zo * p.biasO : nullptr;
    int n = blockIdx.x * 64 + threadIdx.x;
    if (n >= p.N) return;
    float s = 0.f;
    for (int k = 0; k < p.K; k++) s += A[k] * B[(size_t)k * p.ldb + n];
    if (bias) s += bias[n];
    C[n] = s;
}

// ----------------------------- small kernels -------------------------------
__global__ void k_embed(const float* __restrict__ emb, const float* __restrict__ pos,
                        const int* __restrict__ idxs) {
    int tok = blockIdx.x;
    int b = tok >> 9, s = tok & 511;
    int id = (s == 0) ? 0 : idxs[b*SS + s - 1];
    const float4* e  = (const float4*)(emb + (size_t)id * NHID);
    const float4* pr = (const float4*)(pos + (size_t)s  * NHID);
    float4* hr = (float4*)(g_h + (size_t)tok * NHID);
    uint2*  hh = (uint2*)(g_hh + (size_t)tok * NHID);
    int t = threadIdx.x;
    float4 a = e[t], c = pr[t];
    float4 v = make_float4(a.x+c.x, a.y+c.y, a.z+c.z, a.w+c.w);
    hr[t] = v;
    hh[t] = f4h(v);
}

__global__ void k_ln_add(float* __restrict__ out, const float* __restrict__ inp,
                         const float* __restrict__ base, int hgMap,
                         const float* __restrict__ gw, const float* __restrict__ bw,
                         __half* __restrict__ outH, int zg) {
    int n = blockIdx.x;
    int t = threadIdx.x;
    if (zg && n >= NNODE) {                 // fused zg tail: copy h[b][0] rows
        int b = n - NNODE;
        #pragma unroll
        for (int i = 0; i < 4; i++) {
            int c = t + i*128;
            out[(size_t)NNODE*NHID + b*NHID + c] = g_h[((size_t)b*LL) * NHID + c];
        }
        return;
    }
    const float* xr = inp + (size_t)n * NHID;
    size_t brow;
    if (hgMap) { int b = n / SS, s = n % SS; brow = ((size_t)(b*LL + s + 1)) * NHID; }
    else brow = (size_t)n * NHID;
    float x[4];
    #pragma unroll
    for (int i = 0; i < 4; i++) x[i] = xr[t + i*128];
    __shared__ float red[128];
    red[t] = x[0]+x[1]+x[2]+x[3]; __syncthreads();
    for (int s = 64; s > 0; s >>= 1) { if (t < s) red[t] += red[t+s]; __syncthreads(); }
    float mu = red[0] * (1.f/512.f); __syncthreads();
    float d[4], vs = 0.f;
    #pragma unroll
    for (int i = 0; i < 4; i++) { d[i] = x[i] - mu; vs += d[i]*d[i]; }
    red[t] = vs; __syncthreads();
    for (int s = 64; s > 0; s >>= 1) { if (t < s) red[t] += red[t+s]; __syncthreads(); }
    float inv = rsqrtf(red[0] * (1.f/512.f) + 1e-5f);
    #pragma unroll
    for (int i = 0; i < 4; i++) {
        int c = t + i*128;
        float v = base[brow + c] + d[i]*inv*gw[c] + bw[c];
        out[(size_t)n*NHID + c] = v;
        if (outH) outH[(size_t)n*NHID + c] = __float2half_rn(v);
    }
}

__global__ void k_copyxf() {
    int n = blockIdx.x;
    int b = n / SS, s = n % SS;
    const float4* src = (const float4*)(g_h + ((size_t)(b*LL + s + 1)) * NHID);
    uint2* dst = (uint2*)(g_xfh + (size_t)n * NHID);
    dst[threadIdx.x] = f4h(src[threadIdx.x]);
}

__global__ void k_zero_ints() {
    int i = blockIdx.x*blockDim.x + threadIdx.x;
    if (i < 2*NNODE) { g_ind[i] = 0; g_outd[i] = 0; g_cur[i] = 0; }
}

__global__ void k_count2(const int* __restrict__ s0, const int* __restrict__ d0,
                         const int* __restrict__ s1, const int* __restrict__ d1) {
    int gi = blockIdx.y;
    const int* src = gi ? s1 : s0;
    const int* dst = gi ? d1 : d0;
    int e = blockIdx.x*blockDim.x + threadIdx.x;
    if (e < EE) {
        atomicAdd(&g_ind [gi*NNODE + dst[e]], 1);
        atomicAdd(&g_outd[gi*NNODE + src[e]], 1);
    }
}

__global__ void k_scan() {
    __shared__ int sh[1024];
    int gi = blockIdx.x;
    int t = threadIdx.x;
    int base = gi * NNODE;
    int loc[8]; int sum = 0;
    #pragma unroll
    for (int i = 0; i < 8; i++) {
        int idx = t*8 + i;
        int v = (idx < NNODE) ? g_ind[base + idx] : 0;
        loc[i] = sum; sum += v;
    }
    sh[t] = sum; __syncthreads();
    for (int d = 1; d < 1024; d <<= 1) {
        int v = (t >= d) ? sh[t-d] : 0; __syncthreads();
        sh[t] += v; __syncthreads();
    }
    int pre = (t > 0) ? sh[t-1] : 0;
    #pragma unroll
    for (int i = 0; i < 8; i++) {
        int idx = t*8 + i;
        if (idx < NNODE) g_off[base + idx] = pre + loc[i];
    }
}

__global__ void k_scatter2(const int* __restrict__ s0, const int* __restrict__ d0,
                           const int* __restrict__ s1, const int* __restrict__ d1) {
    int gi = blockIdx.y;
    const int* src = gi ? s1 : s0;
    const int* dst = gi ? d1 : d0;
    int e = blockIdx.x*blockDim.x + threadIdx.x;
    if (e < EE) {
        int d = dst[e];
        int p = g_off[gi*NNODE + d] + atomicAdd(&g_cur[gi*NNODE + d], 1);
        g_csr[gi*EE + p] = src[e];
    }
}

__global__ void k_scales() {
    int i = blockIdx.x*blockDim.x + threadIdx.x;
    if (i < 2*NNODE) {
        float in = (float)g_ind[i], od = (float)g_outd[i];
        g_sin [i] = rsqrtf(fmaxf(in, 1.f));
        g_sout[i] = rsqrtf(fmaxf(od, 1.f));
        g_inv1[i] = 1.f / (in + 1.f);
    }
}

__global__ void k_prop_sage(const __half* __restrict__ x, long long xper,
                            __half* __restrict__ out) {
    int gi = blockIdx.y;
    int wid = blockIdx.x * (blockDim.x >> 5) + (threadIdx.x >> 5);
    if (wid >= NNODE) return;
    int lane = threadIdx.x & 31;
    const __half* xb = x + (size_t)gi * xper;
    float a[16];
    #pragma unroll
    for (int i = 0; i < 16; i++) a[i] = 0.f;
    {
        const uint4* xr = (const uint4*)(xb + (size_t)wid * NHID);
        addh8(a, xr[lane], 1.f);
        addh8(a + 8, xr[lane + 32], 1.f);
    }
    int s = g_off[gi*NNODE + wid], e = s + g_ind[gi*NNODE + wid];
    const int* csr = g_csr + gi*EE;
    for (int j = s; j < e; j++) {
        const uint4* sr = (const uint4*)(xb + (size_t)csr[j] * NHID);
        addh8(a, sr[lane], 1.f);
        addh8(a + 8, sr[lane + 32], 1.f);
    }
    float sc = g_inv1[gi*NNODE + wid];
    uint4* o = (uint4*)(out + (size_t)gi * NNODE * NHID + (size_t)wid * NHID);
    o[lane]      = pack8(a, sc);
    o[lane + 32] = pack8(a + 8, sc);
}

__global__ void k_prop_gc(const __half* __restrict__ q, __half* __restrict__ outT) {
    int gi = blockIdx.y;
    int wid = blockIdx.x * (blockDim.x >> 5) + (threadIdx.x >> 5);
    if (wid >= NNODE) return;
    int lane = threadIdx.x & 31;
    const __half* qb = q + (size_t)gi * NNODE * NHID;
    float a[16];
    #pragma unroll
    for (int i = 0; i < 16; i++) a[i] = 0.f;
    float ts = 0.f;
    int s = g_off[gi*NNODE + wid], e = s + g_ind[gi*NNODE + wid];
    const int* csr = g_csr + gi*EE;
    for (int j = s; j < e; j++) {
        int sn = csr[j];
        float so = g_sout[gi*NNODE + sn];
        ts += so;
        const uint4* sr = (const uint4*)(qb + (size_t)sn * NHID);
        addh8(a, sr[lane], so);
        addh8(a + 8, sr[lane + 32], so);
    }
    uint4* o = (uint4*)(outT + (size_t)gi * NNODE * NHID + (size_t)wid * NHID);
    o[lane]      = pack8(a, 1.f);
    o[lane + 32] = pack8(a + 8, 1.f);
    if (lane == 0) g_tvec[gi*NNODE + wid] = ts;
}

// ----------------------------- host orchestration --------------------------
#define SYMF(name, var) { void* _p; cudaGetSymbolAddress(&_p, name); var = (float*)_p; }
#define SYMH(name, var) { void* _p; cudaGetSymbolAddress(&_p, name); var = (__half*)_p; }

extern "C" void kernel_launch(void* const* d_in, const int* in_sizes, int n_in,
                              void* d_out, int out_size) {
    const float* in_embed  = (const float*)d_in[0];
    const float* pos_embed = (const float*)d_in[1];
    const float* qkv_w     = (const float*)d_in[2];
    const float* qkv_b     = (const float*)d_in[3];
    const float* attn_w    = (const float*)d_in[4];
    const float* attn_b    = (const float*)d_in[5];
    const float* ff1_w     = (const float*)d_in[6];
    const float* ff1_b     = (const float*)d_in[7];
    const float* ff2_w     = (const float*)d_in[8];
    const float* ff2_b     = (const float*)d_in[9];
    const float* sage1_w   = (const float*)d_in[10];
    const float* sage1_b   = (const float*)d_in[11];
    const float* sage2_w   = (const float*)d_in[12];
    const float* sage2_b   = (const float*)d_in[13];
    const float* gc3_w     = (const float*)d_in[14];
    const float* gc3_b     = (const float*)d_in[15];
    const float* gff1_w    = (const float*)d_in[16];
    const float* gff1_b    = (const float*)d_in[17];
    const float* gff2_w    = (const float*)d_in[18];
    const float* gff2_b    = (const float*)d_in[19];
    const float* ln_g      = (const float*)d_in[20];
    const float* ln_b      = (const float*)d_in[21];
    const int*   in_idxs   = (const int*)d_in[22];
    const int*   mask      = (const int*)d_in[23];   // bool marshalled as int32
    const int*   gt_src    = (const int*)d_in[24];
    const int*   gt_dst    = (const int*)d_in[25];
    const int*   at_src    = (const int*)d_in[26];
    const int*   at_dst    = (const int*)d_in[27];

    float *h, *x, *xc, *xg, *cc, *dc, *sinp, *tvp;
    SYMF(g_h, h); SYMF(g_x, x); SYMF(g_xc, xc); SYMF(g_xg, xg);
    SYMF(g_ccat, cc); SYMF(g_dcat, dc); SYMF(g_sin, sinp); SYMF(g_tvec, tvp);
    __half *hh, *qkvh, *oh, *xh, *ffh, *xfh, *Ph, *Qh, *Th, *Mh, *Nch, *xgh, *fgh;
    __half *qkvwh, *attnwh, *ff1wh, *ff2wh, *s1wh, *s2wh, *gc3wh, *gff1wh, *gff2wh;
    SYMH(g_hh, hh); SYMH(g_qkvh, qkvh); SYMH(g_oh, oh); SYMH(g_xh, xh); SYMH(g_ffh, ffh);
    SYMH(g_xfh, xfh); SYMH(g_Ph, Ph); SYMH(g_Qh, Qh); SYMH(g_Th, Th);
    SYMH(g_Mh, Mh); SYMH(g_Nch, Nch); SYMH(g_xgh, xgh); SYMH(g_fgh, fgh);
    SYMH(g_qkvwh, qkvwh); SYMH(g_attnwh, attnwh); SYMH(g_ff1wh, ff1wh);
    SYMH(g_ff2wh, ff2wh); SYMH(g_s1wh, s1wh); SYMH(g_s2wh, s2wh);
    SYMH(g_gc3wh, gc3wh); SYMH(g_gff1wh, gff1wh); SYMH(g_gff2wh, gff2wh);

    static int smemSet = 0;
    if (!smemSet) {
        cudaFuncSetAttribute(k_flash, cudaFuncAttributeMaxDynamicSharedMemorySize, FLASH_SMEM);
        cudaFuncSetAttribute(mma_k<128>, cudaFuncAttributeMaxDynamicSharedMemorySize, MMA_SMEM(128));
        cudaFuncSetAttribute(mma_k<64>,  cudaFuncAttributeMaxDynamicSharedMemorySize, MMA_SMEM(64));
        smemSet = 1;
    }

    // ---- fused weight f32 -> f16 (single launch) ----
    {
        TOH9 t;
        const float* srcs[9] = {qkv_w, attn_w, ff1_w, ff2_w, sage1_w, sage2_w,
                                gc3_w, gff1_w, gff2_w};
        __half* dsts[9] = {qkvwh, attnwh, ff1wh, ff2wh, s1wh, s2wh,
                           gc3wh, gff1wh, gff2wh};
        int ns[9] = {4*NHID*QKVD, 4*NHID*NHID, 4*NHID*FFD, 4*FFD*NHID,
                     HEADS*NHID*NHID, HEADS*NHID*NHID, HEADS*NHID*64,
                     NHID*NHID, NHID*NHID};
        int acc = 0;
        for (int i = 0; i < 9; i++) { t.s[i] = srcs[i]; t.d[i] = dsts[i];
                                      t.off[i] = acc; acc += ns[i] / 8; }
        t.off[9] = acc;
        k_tohalf_all<<<(acc + 255)/256, 256>>>(t);
    }

    // ---- embedding + mask packing ----
    k_embed<<<NTOK, 128>>>(in_embed, pos_embed, in_idxs);
    k_packmask<<<BB*LL*HEADS/8, 256>>>(mask);

    // ---- transformer layers ----
    for (int l = 0; l < 4; l++) {
        mgemm(hh, NHID, qkvwh + (size_t)l*NHID*QKVD, QKVD, nullptr, qkvh, QKVD,
              NTOK, QKVD, NHID, qkv_b + l*QKVD);
        k_flash<<<dim3(LL/128, BB*HEADS), 256, FLASH_SMEM>>>();
        mgemm(oh, NHID, attnwh + (size_t)l*NHID*NHID, NHID, x, xh, NHID,
              NTOK, NHID, NHID, attn_b + l*NHID, h, NHID, 2.0f);
        mgemm(xh, NHID, ff1wh + (size_t)l*NHID*FFD, FFD, nullptr, ffh, FFD,
              NTOK, FFD, NHID, ff1_b + l*FFD, nullptr, 0, 0.f, /*relu=*/1);
        mgemm(ffh, FFD, ff2wh + (size_t)l*FFD*NHID, NHID, h, hh, NHID,
              NTOK, NHID, FFD, ff2_b + l*NHID, x, NHID, 1.0f);
    }

    // ---- graph preprocessing (merged launches) ----
    k_zero_ints<<<(2*NNODE + 255)/256, 256>>>();
    k_count2<<<dim3(EE/256, 2), 256>>>(gt_src, gt_dst, at_src, at_dst);
    k_scan<<<2, 1024>>>();
    k_scatter2<<<dim3(EE/256, 2), 256>>>(gt_src, gt_dst, at_src, at_dst);
    k_scales<<<(2*NNODE + 255)/256, 256>>>();
    k_copyxf<<<NNODE, 128>>>();

    // ---- propagations: both graphs per launch, fp16 data ----
    int propBlocks = (NNODE + 7) / 8;
    k_prop_sage<<<dim3(propBlocks, 2), 256>>>(xfh, 0, Ph);
    k_prop_sage<<<dim3(propBlocks, 2), 256>>>(Ph, (long long)NNODE*NHID, Qh);
    k_prop_gc  <<<dim3(propBlocks, 2), 256>>>(Qh, Th);

    // ---- collapse per-head weights ----
    mgemm(s1wh, NHID, s2wh, NHID, nullptr, Mh, NHID, NHID, NHID, NHID,
          nullptr, nullptr, 0, 0.f, 0, HEADS, 1,
          (long long)NHID*NHID, 0, (long long)NHID*NHID, 0, (long long)NHID*NHID, 0);
    mgemm(Mh, NHID, gc3wh, 64, nullptr, Nch, 64, NHID, 64, NHID,
          nullptr, nullptr, 0, 0.f, 0, HEADS, 1,
          (long long)NHID*NHID, 0, (long long)NHID*64, 0, (long long)NHID*64, 0);
    {
        GP p; p.A=sage1_b; p.B=sage2_w; p.bias=sage2_b; p.C=cc;
        p.ldb=NHID; p.N=NHID; p.K=NHID;
        p.aO=NHID; p.bO=(long long)NHID*NHID; p.cO=NHID; p.biasO=NHID;
        gemm1_k<<<dim3((NHID+63)/64,1,HEADS), 64>>>(p);
    }
    {
        GP p; p.A=cc; p.B=gc3_w; p.bias=nullptr; p.C=dc;
        p.ldb=64; p.N=64; p.K=NHID;
        p.aO=NHID; p.bO=(long long)NHID*64; p.cO=64; p.biasO=0;
        gemm1_k<<<dim3(1,1,HEADS), 64>>>(p);
    }

    // ---- xc per head with fused xcepi epilogue ----
    mgemm(Th, NHID, Nch, 64, xc, nullptr, NHID,
          NNODE, 64, NHID, nullptr, nullptr, 0, 0.f, 0,
          HEADS, 1,
          0, (long long)NNODE*NHID,
          (long long)NHID*64, 0,
          64, 0, 0, 0, 0, /*hmode=*/1,
          sinp, tvp, dc, gc3_b);

    // ---- final: xg = hg + LN(xc); ff path; zbar = xg + LN(ff); fused zg ----
    k_ln_add<<<NNODE, 128>>>(xg, xc, h, /*hgMap=*/1, ln_g, ln_b, xgh, 0);
    mgemm(xgh, NHID, gff1wh, NHID, nullptr, fgh, NHID,
          NNODE, NHID, NHID, gff1_b, nullptr, 0, 0.f, /*relu=*/1);
    mgemm(fgh, NHID, gff2wh, NHID, xc, nullptr, NHID,
          NNODE, NHID, NHID, gff2_b);
    int zgTail = (out_size >= NNODE*NHID + BB*NHID) ? 1 : 0;
    k_ln_add<<<NNODE + (zgTail ? BB : 0), 128>>>((float*)d_out, xc, xg,
          /*hgMap=*/0, ln_g, ln_b, nullptr, zgTail);
}

// round 16
// speedup vs baseline: 1.1949x; 1.1949x over previous
#include <cuda_runtime.h>
#include <cuda_fp16.h>
#include <math.h>
#include <stdint.h>

#define NHID   512
#define HEADS  8
#define BB     16
#define SS     511
#define LL     512
#define NNODE  8176
#define NTOK   8192
#define EE     131072
#define QKVD   1536
#define FFD    2048

// ----------------------------- scratch (device globals) --------------------
__device__ float g_h   [NTOK*NHID];
__device__ float g_x   [NTOK*NHID];
__device__ float g_xc  [NNODE*NHID];
__device__ float g_xg  [NNODE*NHID];
__device__ float g_ccat[HEADS*NHID];
__device__ float g_dcat[HEADS*64];
__device__ float g_tvec[2*NNODE];
__device__ float g_sin [2*NNODE];
__device__ float g_sout[2*NNODE];
__device__ float g_inv1[2*NNODE];
__device__ int   g_ind [2*NNODE];
__device__ int   g_outd[2*NNODE];
__device__ int   g_off [2*NNODE];
__device__ int   g_cur [2*NNODE];
__device__ int   g_csr [2*EE];
__device__ unsigned g_pm[(size_t)BB*HEADS*LL*(LL/32)];

// fp16 activations / weights
__device__ __half g_hh  [NTOK*NHID];
__device__ __half g_qkvh[NTOK*QKVD];
__device__ __half g_oh  [NTOK*NHID];
__device__ __half g_xh  [NTOK*NHID];
__device__ __half g_ffh [NTOK*FFD];
__device__ __half g_xfh [NNODE*NHID];
__device__ __half g_Ph  [2*NNODE*NHID];
__device__ __half g_Qh  [2*NNODE*NHID];
__device__ __half g_Th  [2*NNODE*NHID];
__device__ __half g_Mh  [HEADS*NHID*NHID];
__device__ __half g_Nch [HEADS*NHID*64];
__device__ __half g_xgh [NNODE*NHID];
__device__ __half g_fgh [NNODE*NHID];
__device__ __half g_qkvwh [4*NHID*QKVD];
__device__ __half g_attnwh[4*NHID*NHID];
__device__ __half g_ff1wh [4*NHID*FFD];
__device__ __half g_ff2wh [4*FFD*NHID];
__device__ __half g_s1wh  [HEADS*NHID*NHID];
__device__ __half g_s2wh  [HEADS*NHID*NHID];
__device__ __half g_gc3wh [HEADS*NHID*64];
__device__ __half g_gff1wh[NHID*NHID];
__device__ __half g_gff2wh[NHID*NHID];

__constant__ int c_pat[8] = {0,0,1,1,0,0,1,1};

// ----------------------------- helpers -------------------------------------
__device__ __forceinline__ unsigned h2u(float a, float b) {
    __half2 h = __floats2half2_rn(a, b);
    return *reinterpret_cast<unsigned*>(&h);
}
__device__ __forceinline__ uint2 f4h(float4 v) {
    uint2 r; r.x = h2u(v.x, v.y); r.y = h2u(v.z, v.w); return r;
}
__device__ __forceinline__ void addh8(float* a, uint4 u, float s) {
    __half2* hp = (__half2*)&u;
    #pragma unroll
    for (int i = 0; i < 4; i++) {
        float2 f = __half22float2(hp[i]);
        a[2*i]   += f.x * s;
        a[2*i+1] += f.y * s;
    }
}
__device__ __forceinline__ uint4 pack8(const float* a, float s) {
    return make_uint4(h2u(a[0]*s, a[1]*s), h2u(a[2]*s, a[3]*s),
                      h2u(a[4]*s, a[5]*s), h2u(a[6]*s, a[7]*s));
}
__device__ __forceinline__ void ldsm4(unsigned &d0, unsigned &d1, unsigned &d2, unsigned &d3,
                                      unsigned addr) {
    asm volatile("ldmatrix.sync.aligned.m8n8.x4.shared.b16 {%0,%1,%2,%3}, [%4];"
                 : "=r"(d0), "=r"(d1), "=r"(d2), "=r"(d3) : "r"(addr));
}
__device__ __forceinline__ void ldsm4t(unsigned &d0, unsigned &d1, unsigned &d2, unsigned &d3,
                                       unsigned addr) {
    asm volatile("ldmatrix.sync.aligned.m8n8.x4.trans.shared.b16 {%0,%1,%2,%3}, [%4];"
                 : "=r"(d0), "=r"(d1), "=r"(d2), "=r"(d3) : "r"(addr));
}
__device__ __forceinline__ void ldsm2(unsigned &d0, unsigned &d1, unsigned addr) {
    asm volatile("ldmatrix.sync.aligned.m8n8.x2.shared.b16 {%0,%1}, [%2];"
                 : "=r"(d0), "=r"(d1) : "r"(addr));
}
__device__ __forceinline__ void ldsm2t(unsigned &d0, unsigned &d1, unsigned addr) {
    asm volatile("ldmatrix.sync.aligned.m8n8.x2.trans.shared.b16 {%0,%1}, [%2];"
                 : "=r"(d0), "=r"(d1) : "r"(addr));
}
__device__ __forceinline__ void mma16(float* c, const unsigned* a, const unsigned* b) {
    asm volatile(
        "mma.sync.aligned.m16n8k16.row.col.f32.f16.f16.f32 "
        "{%0,%1,%2,%3}, {%4,%5,%6,%7}, {%8,%9}, {%0,%1,%2,%3};"
        : "+f"(c[0]), "+f"(c[1]), "+f"(c[2]), "+f"(c[3])
        : "r"(a[0]), "r"(a[1]), "r"(a[2]), "r"(a[3]), "r"(b[0]), "r"(b[1]));
}
__device__ __forceinline__ void cpa16(unsigned d, const void* s, bool v) {
    asm volatile("cp.async.cg.shared.global [%0], [%1], 16, %2;"
                 :: "r"(d), "l"(s), "r"(v ? 16u : 0u));
}
#define CP_COMMIT asm volatile("cp.async.commit_group;" ::: "memory")
#define CP_WAIT2  asm volatile("cp.async.wait_group 2;" ::: "memory")
#define CP_WAIT0  asm volatile("cp.async.wait_group 0;" ::: "memory")

// ----------------------------- GEMM param block -----------------------------
struct GPH {
    const __half *A, *B;
    const float *bias, *res;
    float *C; __half *Ch;
    const float *sinp, *tvp, *dcp, *g3bp;   // xcepi fusion (hmode)
    int xcepi;
    int lda, ldb, ldc, ldres;
    int M, N, K;
    float resScale;
    int relu;
    int zDiv, hmode;
    int gx, gy, tiles;
    long long aO, aI, bO, bI, cO, cI, rO, rI, biasO;
};
struct GP {
    const float *A, *B, *bias;
    float *C;
    int ldb, N, K;
    long long aO, bO, cO, biasO;
};

// ----------------------------- fp16 cp.async GEMM (persistent, 4-stage) ----
// R14 configuration: K-slice 32, 4 stages, 92 KB smem, 2 CTAs/SM.
template<int BN>
__global__ __launch_bounds__(256, 2) void mma_k(GPH p) {
    constexpr int WGN  = (BN == 128) ? 4 : 2;
    constexpr int WGM  = 8 / WGN;
    constexpr int WM   = 128 / WGM;
    constexpr int WN   = BN / WGN;
    constexpr int MF   = WM / 16;
    constexpr int NF   = WN / 8;
    constexpr int ASTH = 56;
    constexpr int BSTH = BN + 8;
    constexpr int AW   = 128 * ASTH / 2;
    constexpr int BW   = 32 * BSTH / 2;

    extern __shared__ unsigned smw[];
    unsigned sb = (unsigned)__cvta_generic_to_shared(smw);
    unsigned aBase[4], bBase[4];
    #pragma unroll
    for (int s = 0; s < 4; s++) {
        aBase[s] = sb + (unsigned)(s * AW) * 4u;
        bBase[s] = sb + (unsigned)(4 * AW + s * BW) * 4u;
    }

    int tid = threadIdx.x, lane = tid & 31, warp = tid >> 5;
    int wm = warp / WGN, wn = warp % WGN;
    int ar0 = tid >> 2, ac = (tid & 3) * 8;
    int aRow = (lane & 7) + ((lane >> 3) & 1) * 8;
    unsigned aKoff = ((lane >> 4) & 1) * 16;
    int bRowT = (lane & 7) + ((lane >> 3) & 1) * 8;
    int bColT = ((lane >> 4) & 1) * 8;

    for (int t = blockIdx.x; t < p.tiles; t += gridDim.x) {
        int bx = t % p.gx; int rr = t / p.gx;
        int by = rr % p.gy; int bz = rr / p.gy;

        __syncthreads();

        const __half *A, *B;
        float *C = nullptr; __half *Ch = nullptr;
        const float *bias = nullptr, *res = nullptr;
        if (p.hmode) {
            A = p.A + (((bz >> 1) & 1) ? p.aI : 0);
            B = p.B + (size_t)bz * p.bO;
            if (p.C)  C  = p.C  + (size_t)bz * p.cO;
            if (p.Ch) Ch = p.Ch + (size_t)bz * p.cO;
        } else {
            int zo = bz / p.zDiv, zi = bz % p.zDiv;
            A = p.A + zo * p.aO + zi * p.aI;
            B = p.B + zo * p.bO + zi * p.bI;
            if (p.C)  C  = p.C  + zo * p.cO + zi * p.cI;
            if (p.Ch) Ch = p.Ch + zo * p.cO + zi * p.cI;
            if (p.bias) bias = p.bias + zo * p.biasO;
            if (p.res)  res  = p.res + zo * p.rO + zi * p.rI;
        }
        int m0 = bx * 128, n0 = by * BN;
        bool av0 = (m0 + ar0) < p.M, av1 = (m0 + ar0 + 64) < p.M;

        auto issue = [&](int s, int k0) {
            cpa16(aBase[s] + (unsigned)(ar0 * ASTH + ac) * 2u,
                  A + (size_t)(m0 + ar0) * p.lda + k0 + ac, av0);
            cpa16(aBase[s] + (unsigned)((ar0 + 64) * ASTH + ac) * 2u,
                  A + (size_t)(m0 + ar0 + 64) * p.lda + k0 + ac, av1);
            if (BN == 128) {
                int br = tid >> 4, bc = (tid & 15) * 8;
                cpa16(bBase[s] + (unsigned)(br * BSTH + bc) * 2u,
                      B + (size_t)(k0 + br) * p.ldb + n0 + bc, true);
                cpa16(bBase[s] + (unsigned)((br + 16) * BSTH + bc) * 2u,
                      B + (size_t)(k0 + br + 16) * p.ldb + n0 + bc, true);
            } else {
                int br = tid >> 3, bc = (tid & 7) * 8;
                cpa16(bBase[s] + (unsigned)(br * BSTH + bc) * 2u,
                      B + (size_t)(k0 + br) * p.ldb + n0 + bc, true);
            }
        };

        float acc[MF][NF][4];
        #pragma unroll
        for (int f = 0; f < MF; f++)
            #pragma unroll
            for (int j = 0; j < NF; j++)
                #pragma unroll
                for (int q = 0; q < 4; q++) acc[f][j][q] = 0.f;

        int nIter = p.K >> 5;
        issue(0, 0);  CP_COMMIT;
        issue(1, 32); CP_COMMIT;
        issue(2, 64); CP_COMMIT;

        for (int i = 0; i < nIter; i++) {
            CP_WAIT2;
            __syncthreads();
            if (i + 3 < nIter) issue((i + 3) & 3, (i + 3) * 32);
            CP_COMMIT;

            int s = i & 3;
            unsigned aB = aBase[s], bB = bBase[s];
            #pragma unroll
            for (int kk = 0; kk < 32; kk += 16) {
                unsigned bfr[NF][2];
                #pragma unroll
                for (int j = 0; j < NF; j += 2) {
                    unsigned addr = bB + (unsigned)((kk + bRowT) * BSTH
                                  + wn * WN + j * 8 + bColT) * 2u;
                    ldsm4t(bfr[j][0], bfr[j][1], bfr[j+1][0], bfr[j+1][1], addr);
                }
                #pragma unroll
                for (int f = 0; f < MF; f++) {
                    int row = wm * WM + f * 16 + aRow;
                    unsigned addr = aB + (unsigned)(row * ASTH + kk) * 2u + aKoff;
                    unsigned afr[4];
                    ldsm4(afr[0], afr[1], afr[2], afr[3], addr);
                    #pragma unroll
                    for (int j = 0; j < NF; j++) mma16(acc[f][j], afr, bfr[j]);
                }
            }
        }

        // xcepi fusion pointers (hmode)
        const float *sinp = nullptr, *tvp = nullptr, *dcp = nullptr, *g3p = nullptr;
        if (p.xcepi) {
            int g = (bz >> 1) & 1;
            sinp = p.sinp + g * NNODE;
            tvp  = p.tvp  + g * NNODE;
            dcp  = p.dcp  + bz * 64;
            g3p  = p.g3bp + bz * 64;
        }

        #pragma unroll
        for (int f = 0; f < MF; f++) {
            int r0 = m0 + wm * WM + f * 16 + (lane >> 2);
            int r1 = r0 + 8;
            #pragma unroll
            for (int j = 0; j < NF; j++) {
                int col = n0 + wn * WN + j * 8 + 2 * (lane & 3);
                float b0 = 0.f, b1 = 0.f;
                if (bias) { b0 = bias[col]; b1 = bias[col + 1]; }
                float v0 = acc[f][j][0] + b0, v1 = acc[f][j][1] + b1;
                float v2 = acc[f][j][2] + b0, v3 = acc[f][j][3] + b1;
                if (p.relu) {
                    v0 = fmaxf(v0, 0.f); v1 = fmaxf(v1, 0.f);
                    v2 = fmaxf(v2, 0.f); v3 = fmaxf(v3, 0.f);
                }
                if (r0 < p.M) {
                    if (res) {
                        v0 += p.resScale * res[(size_t)r0 * p.ldres + col];
                        v1 += p.resScale * res[(size_t)r0 * p.ldres + col + 1];
                    }
                    if (p.xcepi) {
                        float si = sinp[r0], tv = tvp[r0];
                        v0 = si * v0 + si * tv * dcp[col]     + g3p[col];
                        v1 = si * v1 + si * tv * dcp[col + 1] + g3p[col + 1];
                    }
                    if (C)  *(float2*)&C[(size_t)r0 * p.ldc + col] = make_float2(v0, v1);
                    if (Ch) *(unsigned*)&Ch[(size_t)r0 * p.ldc + col] = h2u(v0, v1);
                }
                if (r1 < p.M) {
                    if (res) {
                        v2 += p.resScale * res[(size_t)r1 * p.ldres + col];
                        v3 += p.resScale * res[(size_t)r1 * p.ldres + col + 1];
                    }
                    if (p.xcepi) {
                        float si = sinp[r1], tv = tvp[r1];
                        v2 = si * v2 + si * tv * dcp[col]     + g3p[col];
                        v3 = si * v3 + si * tv * dcp[col + 1] + g3p[col + 1];
                    }
                    if (C)  *(float2*)&C[(size_t)r1 * p.ldc + col] = make_float2(v2, v3);
                    if (Ch) *(unsigned*)&Ch[(size_t)r1 * p.ldc + col] = h2u(v2, v3);
                }
            }
        }
    }
}

#define MMA_SMEM(BN) ((4 * (128*56/2) + 4 * (32*((BN)+8)/2)) * 4)
#define PERSIST_CTAS 296

static void mgemm(const __half* A, int lda, const __half* B, int ldb,
                  float* C, __half* Ch, int ldc,
                  int M, int N, int K,
                  const float* bias = nullptr, const float* res = nullptr, int ldres = 0,
                  float resScale = 0.f, int relu = 0,
                  int z = 1, int zDiv = 1,
                  long long aO=0, long long aI=0, long long bO=0, long long bI=0,
                  long long cO=0, long long cI=0, long long rO=0, long long rI=0,
                  long long biasO=0, int hmode = 0,
                  const float* sinp = nullptr, const float* tvp = nullptr,
                  const float* dcp = nullptr, const float* g3bp = nullptr) {
    GPH p;
    p.A=A; p.B=B; p.bias=bias; p.res=res; p.C=C; p.Ch=Ch;
    p.sinp=sinp; p.tvp=tvp; p.dcp=dcp; p.g3bp=g3bp; p.xcepi = (sinp != nullptr);
    p.lda=lda; p.ldb=ldb; p.ldc=ldc; p.ldres=ldres;
    p.M=M; p.N=N; p.K=K; p.resScale=resScale; p.relu=relu; p.zDiv=zDiv; p.hmode=hmode;
    p.aO=aO; p.aI=aI; p.bO=bO; p.bI=bI; p.cO=cO; p.cI=cI; p.rO=rO; p.rI=rI; p.biasO=biasO;
    p.gx = (M + 127) / 128;
    if (N % 128 == 0) {
        p.gy = N / 128;
        p.tiles = p.gx * p.gy * z;
        int ctas = p.tiles < PERSIST_CTAS ? p.tiles : PERSIST_CTAS;
        mma_k<128><<<ctas, 256, MMA_SMEM(128)>>>(p);
    } else {
        p.gy = N / 64;
        p.tiles = p.gx * p.gy * z;
        int ctas = p.tiles < PERSIST_CTAS ? p.tiles : PERSIST_CTAS;
        mma_k<64><<<ctas, 256, MMA_SMEM(64)>>>(p);
    }
}

// ----------------------------- fused weight f32->f16 (9 segments) ----------
struct TOH9 {
    const float* s[9];
    __half* d[9];
    int off[10];
};
__global__ void k_tohalf_all(TOH9 t) {
    int g = blockIdx.x * blockDim.x + threadIdx.x;
    if (g >= t.off[9]) return;
    int seg = 0;
    #pragma unroll
    for (int i = 1; i < 9; i++) seg += (g >= t.off[i]);
    int loc = (g - t.off[seg]) * 8;
    const float* in = t.s[seg] + loc;
    __half* out = t.d[seg] + loc;
    uint2 a = f4h(*(const float4*)(in));
    uint2 b = f4h(*(const float4*)(in + 4));
    *(uint4*)(out) = make_uint4(a.x, a.y, b.x, b.y);
}

// ----------------------------- flash attention (fp16, cp.async) ------------
#define KSTW 36
#define FLASH_SMEM ((4*64*KSTW + 128*KSTW) * 4)

__global__ __launch_bounds__(256, 2) void k_flash() {
    extern __shared__ unsigned sm[];
    unsigned sb = (unsigned)__cvta_generic_to_shared(sm);
    unsigned kOff[2] = { sb, sb + 4608u*4u };
    unsigned vOff[2] = { sb + 2304u*4u, sb + 6912u*4u };
    unsigned* sP = sm + 9216;
    unsigned sPb = sb + 9216u*4u;

    int tid = threadIdx.x, lane = tid & 31, w = tid >> 5;
    int m0 = blockIdx.x * 128;
    int bh = blockIdx.y; int h = bh & 7, b = bh >> 3;
    const __half* qb = g_qkvh + (size_t)(b * LL) * QKVD + h * 192;

    int l15 = lane & 15;
    int aRow = (lane & 7) + ((lane >> 3) & 1) * 8;
    unsigned aKoff = ((lane >> 4) & 1) * 16;
    int arow = 16*w + aRow;

    int key = tid >> 2, kc4 = tid & 3;
    auto issue = [&](int st, int kt) {
        const __half* kp = qb + (size_t)(kt*64 + key) * QKVD + 64;
        unsigned kd = kOff[st] + (unsigned)key * 144u;
        cpa16(kd + kc4*16,      kp + kc4*8,       true);
        cpa16(kd + (kc4+4)*16,  kp + (kc4+4)*8,   true);
        unsigned vd = vOff[st] + (unsigned)key * 144u;
        cpa16(vd + kc4*16,      kp + 64 + kc4*8,  true);
        cpa16(vd + (kc4+4)*16,  kp + 64 + (kc4+4)*8, true);
    };

    issue(0, 0); CP_COMMIT;

    {
        int row = tid >> 1, dh = (tid & 1) * 32;
        const uint4* src = (const uint4*)(qb + (size_t)(m0 + row) * QKVD + dh);
        unsigned* dst = sP + row * KSTW + dh/2;
        #pragma unroll
        for (int c = 0; c < 4; c++) *(uint4*)(dst + c*4) = src[c];
    }
    __syncthreads();
    unsigned qf[4][4];
    #pragma unroll
    for (int kc = 0; kc < 4; kc++)
        ldsm4(qf[kc][0], qf[kc][1], qf[kc][2], qf[kc][3],
              sPb + (unsigned)(arow * KSTW) * 4u + (unsigned)kc * 32u + aKoff);

    float accO[8][4];
    #pragma unroll
    for (int j = 0; j < 8; j++)
        #pragma unroll
        for (int q = 0; q < 4; q++) accO[j][q] = 0.f;
    float m0r = -INFINITY, m1r = -INFINITY, l0r = 0.f, l1r = 0.f;

    const unsigned* pmr0 = g_pm + ((size_t)bh * LL + m0 + 16*w + (lane >> 2)) * 16;
    const unsigned* pmr1 = pmr0 + 8 * 16;

    for (int kt = 0; kt < 8; kt++) {
        CP_WAIT0;
        __syncthreads();
        if (kt + 1 < 8) { issue((kt + 1) & 1, kt + 1); CP_COMMIT; }
        int st = kt & 1;

        float S[8][4];
        #pragma unroll
        for (int nt = 0; nt < 8; nt++)
            #pragma unroll
            for (int q = 0; q < 4; q++) S[nt][q] = 0.f;
        #pragma unroll
        for (int kc = 0; kc < 4; kc++) {
            #pragma unroll
            for (int nt = 0; nt < 8; nt++) {
                unsigned bb[2];
                unsigned addr = kOff[st] + (unsigned)((nt*8 + (l15 & 7)) * KSTW) * 4u
                                        + (unsigned)kc * 32u + (unsigned)(l15 >> 3) * 16u;
                ldsm2(bb[0], bb[1], addr);
                mma16(S[nt], qf[kc], bb);
            }
        }

        uint2 mw0 = *(const uint2*)(pmr0 + kt*2);
        uint2 mw1 = *(const uint2*)(pmr1 + kt*2);
        unsigned q0[2] = {mw0.x, mw0.y};
        unsigned q1[2] = {mw1.x, mw1.y};
        float rm0 = -INFINITY, rm1 = -INFINITY;
        #pragma unroll
        for (int nt = 0; nt < 8; nt++) {
            int j0 = nt*8 + 2*(lane & 3), j1 = j0 + 1;
            S[nt][0] = ((q0[j0>>5] >> (j0&31)) & 1u) ? S[nt][0]*0.125f : -INFINITY;
            S[nt][1] = ((q0[j1>>5] >> (j1&31)) & 1u) ? S[nt][1]*0.125f : -INFINITY;
            S[nt][2] = ((q1[j0>>5] >> (j0&31)) & 1u) ? S[nt][2]*0.125f : -INFINITY;
            S[nt][3] = ((q1[j1>>5] >> (j1&31)) & 1u) ? S[nt][3]*0.125f : -INFINITY;
            rm0 = fmaxf(rm0, fmaxf(S[nt][0], S[nt][1]));
            rm1 = fmaxf(rm1, fmaxf(S[nt][2], S[nt][3]));
        }
        rm0 = fmaxf(rm0, __shfl_xor_sync(0xffffffffu, rm0, 1));
        rm0 = fmaxf(rm0, __shfl_xor_sync(0xffffffffu, rm0, 2));
        rm1 = fmaxf(rm1, __shfl_xor_sync(0xffffffffu, rm1, 1));
        rm1 = fmaxf(rm1, __shfl_xor_sync(0xffffffffu, rm1, 2));

        float mn0 = fmaxf(m0r, rm0), mn1 = fmaxf(m1r, rm1);
        float a0 = __expf(m0r - mn0), a1 = __expf(m1r - mn1);
        m0r = mn0; m1r = mn1;

        int prow0 = 16*w + (lane >> 2), prow1 = prow0 + 8;
        float rs0 = 0.f, rs1 = 0.f;
        #pragma unroll
        for (int nt = 0; nt < 8; nt++) {
            int jw = nt*4 + (lane & 3);
            float p00 = __expf(S[nt][0] - mn0), p01 = __expf(S[nt][1] - mn0);
            float p10 = __expf(S[nt][2] - mn1), p11 = __expf(S[nt][3] - mn1);
            rs0 += p00 + p01; rs1 += p10 + p11;
            sP[prow0*KSTW + jw] = h2u(p00, p01);
            sP[prow1*KSTW + jw] = h2u(p10, p11);
        }
        rs0 += __shfl_xor_sync(0xffffffffu, rs0, 1);
        rs0 += __shfl_xor_sync(0xffffffffu, rs0, 2);
        rs1 += __shfl_xor_sync(0xffffffffu, rs1, 1);
        rs1 += __shfl_xor_sync(0xffffffffu, rs1, 2);
        l0r = l0r * a0 + rs0;
        l1r = l1r * a1 + rs1;

        #pragma unroll
        for (int j = 0; j < 8; j++) {
            accO[j][0] *= a0; accO[j][1] *= a0;
            accO[j][2] *= a1; accO[j][3] *= a1;
        }
        __syncwarp();

        #pragma unroll
        for (int kc = 0; kc < 4; kc++) {
            unsigned pf[4];
            ldsm4(pf[0], pf[1], pf[2], pf[3],
                  sPb + (unsigned)(arow * KSTW) * 4u + (unsigned)kc * 32u + aKoff);
            #pragma unroll
            for (int nt = 0; nt < 8; nt++) {
                unsigned bb[2];
                unsigned addr = vOff[st] + (unsigned)((kc*16 + (l15 & 7) + (l15 >> 3)*8) * KSTW) * 4u
                                        + (unsigned)nt * 16u;
                ldsm2t(bb[0], bb[1], addr);
                mma16(accO[nt], pf, bb);
            }
        }
    }

    float inv0 = 1.f / l0r, inv1 = 1.f / l1r;
    int r0 = m0 + 16*w + (lane >> 2), r1 = r0 + 8;
    __half* o0 = g_oh + (size_t)(b*LL + r0) * NHID + h*64;
    __half* o1 = g_oh + (size_t)(b*LL + r1) * NHID + h*64;
    #pragma unroll
    for (int nt = 0; nt < 8; nt++) {
        int col = nt*8 + 2*(lane & 3);
        *(unsigned*)&o0[col] = h2u(accO[nt][0]*inv0, accO[nt][1]*inv0);
        *(unsigned*)&o1[col] = h2u(accO[nt][2]*inv1, accO[nt][3]*inv1);
    }
}

// pack mask (int32 bool, layout [b][i][h][j]) -> bits [b][h][i][j/32]
__global__ void k_packmask(const int* __restrict__ mask) {
    int row = blockIdx.x * 8 + (threadIdx.x >> 5);
    int lane = threadIdx.x & 31;
    const int* mr = mask + (size_t)row * LL;
    int b_i = row >> 3, h = row & 7;
    int b = b_i >> 9, i = b_i & 511;
    unsigned* out = g_pm + (((size_t)(b*HEADS + h) * LL + i) << 4);
    #pragma unroll
    for (int wd = 0; wd < 16; wd++) {
        unsigned bits = __ballot_sync(0xffffffffu, mr[wd*32 + lane] != 0);
        if (lane == 0) out[wd] = bits;
    }
}

// ----------------------------- small FFMA GEMM (M=1) -----------------------
__global__ void gemm1_k(GP p) {
    int zo = blockIdx.z;
    const float* A = p.A + zo * p.aO;
    const float* B = p.B + zo * p.bO;
    float* C = p.C + zo * p.cO;
    const float* bias = p.bias ? p.bias + zo * p.biasO : nullptr;
    int n = blockIdx.x * 64 + threadIdx.x;
    if (n >= p.N) return;
    float s = 0.f;
    for (int k = 0; k < p.K; k++) s += A[k] * B[(size_t)k * p.ldb + n];
    if (bias) s += bias[n];
    C[n] = s;
}

// ----------------------------- small kernels -------------------------------
__global__ void k_embed(const float* __restrict__ emb, const float* __restrict__ pos,
                        const int* __restrict__ idxs) {
    int tok = blockIdx.x;
    int b = tok >> 9, s = tok & 511;
    int id = (s == 0) ? 0 : idxs[b*SS + s - 1];
    const float4* e  = (const float4*)(emb + (size_t)id * NHID);
    const float4* pr = (const float4*)(pos + (size_t)s  * NHID);
    float4* hr = (float4*)(g_h + (size_t)tok * NHID);
    uint2*  hh = (uint2*)(g_hh + (size_t)tok * NHID);
    int t = threadIdx.x;
    float4 a = e[t], c = pr[t];
    float4 v = make_float4(a.x+c.x, a.y+c.y, a.z+c.z, a.w+c.w);
    hr[t] = v;
    hh[t] = f4h(v);
}

__global__ void k_ln_add(float* __restrict__ out, const float* __restrict__ inp,
                         const float* __restrict__ base, int hgMap,
                         const float* __restrict__ gw, const float* __restrict__ bw,
                         __half* __restrict__ outH, int zg) {
    int n = blockIdx.x;
    int t = threadIdx.x;
    if (zg && n >= NNODE) {                 // fused zg tail: copy h[b][0] rows
        int b = n - NNODE;
        #pragma unroll
        for (int i = 0; i < 4; i++) {
            int c = t + i*128;
            out[(size_t)NNODE*NHID + b*NHID + c] = g_h[((size_t)b*LL) * NHID + c];
        }
        return;
    }
    const float* xr = inp + (size_t)n * NHID;
    size_t brow;
    if (hgMap) { int b = n / SS, s = n % SS; brow = ((size_t)(b*LL + s + 1)) * NHID; }
    else brow = (size_t)n * NHID;
    float x[4];
    #pragma unroll
    for (int i = 0; i < 4; i++) x[i] = xr[t + i*128];
    __shared__ float red[128];
    red[t] = x[0]+x[1]+x[2]+x[3]; __syncthreads();
    for (int s = 64; s > 0; s >>= 1) { if (t < s) red[t] += red[t+s]; __syncthreads(); }
    float mu = red[0] * (1.f/512.f); __syncthreads();
    float d[4], vs = 0.f;
    #pragma unroll
    for (int i = 0; i < 4; i++) { d[i] = x[i] - mu; vs += d[i]*d[i]; }
    red[t] = vs; __syncthreads();
    for (int s = 64; s > 0; s >>= 1) { if (t < s) red[t] += red[t+s]; __syncthreads(); }
    float inv = rsqrtf(red[0] * (1.f/512.f) + 1e-5f);
    #pragma unroll
    for (int i = 0; i < 4; i++) {
        int c = t + i*128;
        float v = base[brow + c] + d[i]*inv*gw[c] + bw[c];
        out[(size_t)n*NHID + c] = v;
        if (outH) outH[(size_t)n*NHID + c] = __float2half_rn(v);
    }
}

__global__ void k_copyxf() {
    int n = blockIdx.x;
    int b = n / SS, s = n % SS;
    const float4* src = (const float4*)(g_h + ((size_t)(b*LL + s + 1)) * NHID);
    uint2* dst = (uint2*)(g_xfh + (size_t)n * NHID);
    dst[threadIdx.x] = f4h(src[threadIdx.x]);
}

__global__ void k_zero_ints() {
    int i = blockIdx.x*blockDim.x + threadIdx.x;
    if (i < 2*NNODE) { g_ind[i] = 0; g_outd[i] = 0; g_cur[i] = 0; }
}

__global__ void k_count2(const int* __restrict__ s0, const int* __restrict__ d0,
                         const int* __restrict__ s1, const int* __restrict__ d1) {
    int gi = blockIdx.y;
    const int* src = gi ? s1 : s0;
    const int* dst = gi ? d1 : d0;
    int e = blockIdx.x*blockDim.x + threadIdx.x;
    if (e < EE) {
        atomicAdd(&g_ind [gi*NNODE + dst[e]], 1);
        atomicAdd(&g_outd[gi*NNODE + src[e]], 1);
    }
}

__global__ void k_scan() {
    __shared__ int sh[1024];
    int gi = blockIdx.x;
    int t = threadIdx.x;
    int base = gi * NNODE;
    int loc[8]; int sum = 0;
    #pragma unroll
    for (int i = 0; i < 8; i++) {
        int idx = t*8 + i;
        int v = (idx < NNODE) ? g_ind[base + idx] : 0;
        loc[i] = sum; sum += v;
    }
    sh[t] = sum; __syncthreads();
    for (int d = 1; d < 1024; d <<= 1) {
        int v = (t >= d) ? sh[t-d] : 0; __syncthreads();
        sh[t] += v; __syncthreads();
    }
    int pre = (t > 0) ? sh[t-1] : 0;
    #pragma unroll
    for (int i = 0; i < 8; i++) {
        int idx = t*8 + i;
        if (idx < NNODE) g_off[base + idx] = pre + loc[i];
    }
}

__global__ void k_scatter2(const int* __restrict__ s0, const int* __restrict__ d0,
                           const int* __restrict__ s1, const int* __restrict__ d1) {
    int gi = blockIdx.y;
    const int* src = gi ? s1 : s0;
    const int* dst = gi ? d1 : d0;
    int e = blockIdx.x*blockDim.x + threadIdx.x;
    if (e < EE) {
        int d = dst[e];
        int p = g_off[gi*NNODE + d] + atomicAdd(&g_cur[gi*NNODE + d], 1);
        g_csr[gi*EE + p] = src[e];
    }
}

__global__ void k_scales() {
    int i = blockIdx.x*blockDim.x + threadIdx.x;
    if (i < 2*NNODE) {
        float in = (float)g_ind[i], od = (float)g_outd[i];
        g_sin [i] = rsqrtf(fmaxf(in, 1.f));
        g_sout[i] = rsqrtf(fmaxf(od, 1.f));
        g_inv1[i] = 1.f / (in + 1.f);
    }
}

__global__ void k_prop_sage(const __half* __restrict__ x, long long xper,
                            __half* __restrict__ out) {
    int gi = blockIdx.y;
    int wid = blockIdx.x * (blockDim.x >> 5) + (threadIdx.x >> 5);
    if (wid >= NNODE) return;
    int lane = threadIdx.x & 31;
    const __half* xb = x + (size_t)gi * xper;
    float a[16];
    #pragma unroll
    for (int i = 0; i < 16; i++) a[i] = 0.f;
    {
        const uint4* xr = (const uint4*)(xb + (size_t)wid * NHID);
        addh8(a, xr[lane], 1.f);
        addh8(a + 8, xr[lane + 32], 1.f);
    }
    int s = g_off[gi*NNODE + wid], e = s + g_ind[gi*NNODE + wid];
    const int* csr = g_csr + gi*EE;
    for (int j = s; j < e; j++) {
        const uint4* sr = (const uint4*)(xb + (size_t)csr[j] * NHID);
        addh8(a, sr[lane], 1.f);
        addh8(a + 8, sr[lane + 32], 1.f);
    }
    float sc = g_inv1[gi*NNODE + wid];
    uint4* o = (uint4*)(out + (size_t)gi * NNODE * NHID + (size_t)wid * NHID);
    o[lane]      = pack8(a, sc);
    o[lane + 32] = pack8(a + 8, sc);
}

__global__ void k_prop_gc(const __half* __restrict__ q, __half* __restrict__ outT) {
    int gi = blockIdx.y;
    int wid = blockIdx.x * (blockDim.x >> 5) + (threadIdx.x >> 5);
    if (wid >= NNODE) return;
    int lane = threadIdx.x & 31;
    const __half* qb = q + (size_t)gi * NNODE * NHID;
    float a[16];
    #pragma unroll
    for (int i = 0; i < 16; i++) a[i] = 0.f;
    float ts = 0.f;
    int s = g_off[gi*NNODE + wid], e = s + g_ind[gi*NNODE + wid];
    const int* csr = g_csr + gi*EE;
    for (int j = s; j < e; j++) {
        int sn = csr[j];
        float so = g_sout[gi*NNODE + sn];
        ts += so;
        const uint4* sr = (const uint4*)(qb + (size_t)sn * NHID);
        addh8(a, sr[lane], so);
        addh8(a + 8, sr[lane + 32], so);
    }
    uint4* o = (uint4*)(outT + (size_t)gi * NNODE * NHID + (size_t)wid * NHID);
    o[lane]      = pack8(a, 1.f);
    o[lane + 32] = pack8(a + 8, 1.f);
    if (lane == 0) g_tvec[gi*NNODE + wid] = ts;
}

// ----------------------------- host orchestration --------------------------
#define SYMF(name, var) { void* _p; cudaGetSymbolAddress(&_p, name); var = (float*)_p; }
#define SYMH(name, var) { void* _p; cudaGetSymbolAddress(&_p, name); var = (__half*)_p; }

extern "C" void kernel_launch(void* const* d_in, const int* in_sizes, int n_in,
                              void* d_out, int out_size) {
    const float* in_embed  = (const float*)d_in[0];
    const float* pos_embed = (const float*)d_in[1];
    const float* qkv_w     = (const float*)d_in[2];
    const float* qkv_b     = (const float*)d_in[3];
    const float* attn_w    = (const float*)d_in[4];
    const float* attn_b    = (const float*)d_in[5];
    const float* ff1_w     = (const float*)d_in[6];
    const float* ff1_b     = (const float*)d_in[7];
    const float* ff2_w     = (const float*)d_in[8];
    const float* ff2_b     = (const float*)d_in[9];
    const float* sage1_w   = (const float*)d_in[10];
    const float* sage1_b   = (const float*)d_in[11];
    const float* sage2_w   = (const float*)d_in[12];
    const float* sage2_b   = (const float*)d_in[13];
    const float* gc3_w     = (const float*)d_in[14];
    const float* gc3_b     = (const float*)d_in[15];
    const float* gff1_w    = (const float*)d_in[16];
    const float* gff1_b    = (const float*)d_in[17];
    const float* gff2_w    = (const float*)d_in[18];
    const float* gff2_b    = (const float*)d_in[19];
    const float* ln_g      = (const float*)d_in[20];
    const float* ln_b      = (const float*)d_in[21];
    const int*   in_idxs   = (const int*)d_in[22];
    const int*   mask      = (const int*)d_in[23];   // bool marshalled as int32
    const int*   gt_src    = (const int*)d_in[24];
    const int*   gt_dst    = (const int*)d_in[25];
    const int*   at_src    = (const int*)d_in[26];
    const int*   at_dst    = (const int*)d_in[27];

    float *h, *x, *xc, *xg, *cc, *dc, *sinp, *tvp;
    SYMF(g_h, h); SYMF(g_x, x); SYMF(g_xc, xc); SYMF(g_xg, xg);
    SYMF(g_ccat, cc); SYMF(g_dcat, dc); SYMF(g_sin, sinp); SYMF(g_tvec, tvp);
    __half *hh, *qkvh, *oh, *xh, *ffh, *xfh, *Ph, *Qh, *Th, *Mh, *Nch, *xgh, *fgh;
    __half *qkvwh, *attnwh, *ff1wh, *ff2wh, *s1wh, *s2wh, *gc3wh, *gff1wh, *gff2wh;
    SYMH(g_hh, hh); SYMH(g_qkvh, qkvh); SYMH(g_oh, oh); SYMH(g_xh, xh); SYMH(g_ffh, ffh);
    SYMH(g_xfh, xfh); SYMH(g_Ph, Ph); SYMH(g_Qh, Qh); SYMH(g_Th, Th);
    SYMH(g_Mh, Mh); SYMH(g_Nch, Nch); SYMH(g_xgh, xgh); SYMH(g_fgh, fgh);
    SYMH(g_qkvwh, qkvwh); SYMH(g_attnwh, attnwh); SYMH(g_ff1wh, ff1wh);
    SYMH(g_ff2wh, ff2wh); SYMH(g_s1wh, s1wh); SYMH(g_s2wh, s2wh);
    SYMH(g_gc3wh, gc3wh); SYMH(g_gff1wh, gff1wh); SYMH(g_gff2wh, gff2wh);

    static int smemSet = 0;
    if (!smemSet) {
        cudaFuncSetAttribute(k_flash, cudaFuncAttributeMaxDynamicSharedMemorySize, FLASH_SMEM);
        cudaFuncSetAttribute(mma_k<128>, cudaFuncAttributeMaxDynamicSharedMemorySize, MMA_SMEM(128));
        cudaFuncSetAttribute(mma_k<64>,  cudaFuncAttributeMaxDynamicSharedMemorySize, MMA_SMEM(64));
        smemSet = 1;
    }

    // ---- fused weight f32 -> f16 (single launch) ----
    {
        TOH9 t;
        const float* srcs[9] = {qkv_w, attn_w, ff1_w, ff2_w, sage1_w, sage2_w,
                                gc3_w, gff1_w, gff2_w};
        __half* dsts[9] = {qkvwh, attnwh, ff1wh, ff2wh, s1wh, s2wh,
                           gc3wh, gff1wh, gff2wh};
        int ns[9] = {4*NHID*QKVD, 4*NHID*NHID, 4*NHID*FFD, 4*FFD*NHID,
                     HEADS*NHID*NHID, HEADS*NHID*NHID, HEADS*NHID*64,
                     NHID*NHID, NHID*NHID};
        int acc = 0;
        for (int i = 0; i < 9; i++) { t.s[i] = srcs[i]; t.d[i] = dsts[i];
                                      t.off[i] = acc; acc += ns[i] / 8; }
        t.off[9] = acc;
        k_tohalf_all<<<(acc + 255)/256, 256>>>(t);
    }

    // ---- embedding + mask packing ----
    k_embed<<<NTOK, 128>>>(in_embed, pos_embed, in_idxs);
    k_packmask<<<BB*LL*HEADS/8, 256>>>(mask);

    // ---- transformer layers ----
    for (int l = 0; l < 4; l++) {
        mgemm(hh, NHID, qkvwh + (size_t)l*NHID*QKVD, QKVD, nullptr, qkvh, QKVD,
              NTOK, QKVD, NHID, qkv_b + l*QKVD);
        k_flash<<<dim3(LL/128, BB*HEADS), 256, FLASH_SMEM>>>();
        mgemm(oh, NHID, attnwh + (size_t)l*NHID*NHID, NHID, x, xh, NHID,
              NTOK, NHID, NHID, attn_b + l*NHID, h, NHID, 2.0f);
        mgemm(xh, NHID, ff1wh + (size_t)l*NHID*FFD, FFD, nullptr, ffh, FFD,
              NTOK, FFD, NHID, ff1_b + l*FFD, nullptr, 0, 0.f, /*relu=*/1);
        mgemm(ffh, FFD, ff2wh + (size_t)l*FFD*NHID, NHID, h, hh, NHID,
              NTOK, NHID, FFD, ff2_b + l*NHID, x, NHID, 1.0f);
    }

    // ---- graph preprocessing (merged launches) ----
    k_zero_ints<<<(2*NNODE + 255)/256, 256>>>();
    k_count2<<<dim3(EE/256, 2), 256>>>(gt_src, gt_dst, at_src, at_dst);
    k_scan<<<2, 1024>>>();
    k_scatter2<<<dim3(EE/256, 2), 256>>>(gt_src, gt_dst, at_src, at_dst);
    k_scales<<<(2*NNODE + 255)/256, 256>>>();
    k_copyxf<<<NNODE, 128>>>();

    // ---- propagations: both graphs per launch, fp16 data ----
    int propBlocks = (NNODE + 7) / 8;
    k_prop_sage<<<dim3(propBlocks, 2), 256>>>(xfh, 0, Ph);
    k_prop_sage<<<dim3(propBlocks, 2), 256>>>(Ph, (long long)NNODE*NHID, Qh);
    k_prop_gc  <<<dim3(propBlocks, 2), 256>>>(Qh, Th);

    // ---- collapse per-head weights ----
    mgemm(s1wh, NHID, s2wh, NHID, nullptr, Mh, NHID, NHID, NHID, NHID,
          nullptr, nullptr, 0, 0.f, 0, HEADS, 1,
          (long long)NHID*NHID, 0, (long long)NHID*NHID, 0, (long long)NHID*NHID, 0);
    mgemm(Mh, NHID, gc3wh, 64, nullptr, Nch, 64, NHID, 64, NHID,
          nullptr, nullptr, 0, 0.f, 0, HEADS, 1,
          (long long)NHID*NHID, 0, (long long)NHID*64, 0, (long long)NHID*64, 0);
    {
        GP p; p.A=sage1_b; p.B=sage2_w; p.bias=sage2_b; p.C=cc;
        p.ldb=NHID; p.N=NHID; p.K=NHID;
        p.aO=NHID; p.bO=(long long)NHID*NHID; p.cO=NHID; p.biasO=NHID;
        gemm1_k<<<dim3((NHID+63)/64,1,HEADS), 64>>>(p);
    }
    {
        GP p; p.A=cc; p.B=gc3_w; p.bias=nullptr; p.C=dc;
        p.ldb=64; p.N=64; p.K=NHID;
        p.aO=NHID; p.bO=(long long)NHID*64; p.cO=64; p.biasO=0;
        gemm1_k<<<dim3(1,1,HEADS), 64>>>(p);
    }

    // ---- xc per head with fused xcepi epilogue ----
    mgemm(Th, NHID, Nch, 64, xc, nullptr, NHID,
          NNODE, 64, NHID, nullptr, nullptr, 0, 0.f, 0,
          HEADS, 1,
          0, (long long)NNODE*NHID,
          (long long)NHID*64, 0,
          64, 0, 0, 0, 0, /*hmode=*/1,
          sinp, tvp, dc, gc3_b);

    // ---- final: xg = hg + LN(xc); ff path; zbar = xg + LN(ff); fused zg ----
    k_ln_add<<<NNODE, 128>>>(xg, xc, h, /*hgMap=*/1, ln_g, ln_b, xgh, 0);
    mgemm(xgh, NHID, gff1wh, NHID, nullptr, fgh, NHID,
          NNODE, NHID, NHID, gff1_b, nullptr, 0, 0.f, /*relu=*/1);
    mgemm(fgh, NHID, gff2wh, NHID, xc, nullptr, NHID,
          NNODE, NHID, NHID, gff2_b);
    int zgTail = (out_size >= NNODE*NHID + BB*NHID) ? 1 : 0;
    k_ln_add<<<NNODE + (zgTail ? BB : 0), 128>>>((float*)d_out, xc, xg,
          /*hgMap=*/0, ln_g, ln_b, nullptr, zgTail);
}

// round 17
// speedup vs baseline: 1.2586x; 1.0533x over previous
#include <cuda_runtime.h>
#include <cuda_fp16.h>
#include <math.h>
#include <stdint.h>

#define NHID   512
#define HEADS  8
#define BB     16
#define SS     511
#define LL     512
#define NNODE  8176
#define NTOK   8192
#define EE     131072
#define QKVD   1536
#define FFD    2048

// ----------------------------- scratch (device globals) --------------------
__device__ float g_h   [NTOK*NHID];
__device__ float g_x   [NTOK*NHID];
__device__ float g_xc  [NNODE*NHID];
__device__ float g_xg  [NNODE*NHID];
__device__ float g_ccat[HEADS*NHID];
__device__ float g_dcat[HEADS*64];
__device__ float g_tvec[2*NNODE];
__device__ float g_sin [2*NNODE];
__device__ float g_sout[2*NNODE];
__device__ float g_inv1[2*NNODE];
__device__ int   g_ind [2*NNODE];
__device__ int   g_outd[2*NNODE];
__device__ int   g_off [2*NNODE];
__device__ int   g_cur [2*NNODE];
__device__ int   g_csr [2*EE];
__device__ unsigned g_pm[(size_t)BB*HEADS*LL*(LL/32)];

// fp16 activations / weights
__device__ __half g_hh  [NTOK*NHID];
__device__ __half g_qkvh[NTOK*QKVD];
__device__ __half g_oh  [NTOK*NHID];
__device__ __half g_xh  [NTOK*NHID];
__device__ __half g_ffh [NTOK*FFD];
__device__ __half g_xfh [NNODE*NHID];
__device__ __half g_Ph  [2*NNODE*NHID];
__device__ __half g_Qh  [2*NNODE*NHID];
__device__ __half g_Th  [2*NNODE*NHID];
__device__ __half g_Mh  [HEADS*NHID*NHID];
__device__ __half g_Nch [HEADS*NHID*64];
__device__ __half g_xgh [NNODE*NHID];
__device__ __half g_fgh [NNODE*NHID];
__device__ __half g_qkvwh [4*NHID*QKVD];
__device__ __half g_attnwh[4*NHID*NHID];
__device__ __half g_ff1wh [4*NHID*FFD];
__device__ __half g_ff2wh [4*FFD*NHID];
__device__ __half g_s1wh  [HEADS*NHID*NHID];
__device__ __half g_s2wh  [HEADS*NHID*NHID];
__device__ __half g_gc3wh [HEADS*NHID*64];
__device__ __half g_gff1wh[NHID*NHID];
__device__ __half g_gff2wh[NHID*NHID];

__constant__ int c_pat[8] = {0,0,1,1,0,0,1,1};

// ----------------------------- helpers -------------------------------------
__device__ __forceinline__ unsigned h2u(float a, float b) {
    __half2 h = __floats2half2_rn(a, b);
    return *reinterpret_cast<unsigned*>(&h);
}
__device__ __forceinline__ uint2 f4h(float4 v) {
    uint2 r; r.x = h2u(v.x, v.y); r.y = h2u(v.z, v.w); return r;
}
__device__ __forceinline__ void addh8(float* a, uint4 u, float s) {
    __half2* hp = (__half2*)&u;
    #pragma unroll
    for (int i = 0; i < 4; i++) {
        float2 f = __half22float2(hp[i]);
        a[2*i]   += f.x * s;
        a[2*i+1] += f.y * s;
    }
}
__device__ __forceinline__ uint4 pack8(const float* a, float s) {
    return make_uint4(h2u(a[0]*s, a[1]*s), h2u(a[2]*s, a[3]*s),
                      h2u(a[4]*s, a[5]*s), h2u(a[6]*s, a[7]*s));
}
__device__ __forceinline__ void ldsm4(unsigned &d0, unsigned &d1, unsigned &d2, unsigned &d3,
                                      unsigned addr) {
    asm volatile("ldmatrix.sync.aligned.m8n8.x4.shared.b16 {%0,%1,%2,%3}, [%4];"
                 : "=r"(d0), "=r"(d1), "=r"(d2), "=r"(d3) : "r"(addr));
}
__device__ __forceinline__ void ldsm4t(unsigned &d0, unsigned &d1, unsigned &d2, unsigned &d3,
                                       unsigned addr) {
    asm volatile("ldmatrix.sync.aligned.m8n8.x4.trans.shared.b16 {%0,%1,%2,%3}, [%4];"
                 : "=r"(d0), "=r"(d1), "=r"(d2), "=r"(d3) : "r"(addr));
}
__device__ __forceinline__ void ldsm2(unsigned &d0, unsigned &d1, unsigned addr) {
    asm volatile("ldmatrix.sync.aligned.m8n8.x2.shared.b16 {%0,%1}, [%2];"
                 : "=r"(d0), "=r"(d1) : "r"(addr));
}
__device__ __forceinline__ void ldsm2t(unsigned &d0, unsigned &d1, unsigned addr) {
    asm volatile("ldmatrix.sync.aligned.m8n8.x2.trans.shared.b16 {%0,%1}, [%2];"
                 : "=r"(d0), "=r"(d1) : "r"(addr));
}
__device__ __forceinline__ void mma16(float* c, const unsigned* a, const unsigned* b) {
    asm volatile(
        "mma.sync.aligned.m16n8k16.row.col.f32.f16.f16.f32 "
        "{%0,%1,%2,%3}, {%4,%5,%6,%7}, {%8,%9}, {%0,%1,%2,%3};"
        : "+f"(c[0]), "+f"(c[1]), "+f"(c[2]), "+f"(c[3])
        : "r"(a[0]), "r"(a[1]), "r"(a[2]), "r"(a[3]), "r"(b[0]), "r"(b[1]));
}
__device__ __forceinline__ void cpa16(unsigned d, const void* s, bool v) {
    asm volatile("cp.async.cg.shared.global [%0], [%1], 16, %2;"
                 :: "r"(d), "l"(s), "r"(v ? 16u : 0u));
}
#define CP_COMMIT asm volatile("cp.async.commit_group;" ::: "memory")
#define CP_WAIT2  asm volatile("cp.async.wait_group 2;" ::: "memory")
#define CP_WAIT0  asm volatile("cp.async.wait_group 0;" ::: "memory")

// ----------------------------- GEMM param block -----------------------------
struct GPH {
    const __half *A, *B;
    const float *bias, *res;
    float *C; __half *Ch;
    int lda, ldb, ldc, ldres;
    int M, N, K;
    float resScale;
    int relu;
    int zDiv, hmode;
    int gx, gy, tiles;
    long long aO, aI, bO, bI, cO, cI, rO, rI, biasO;
};
struct GP {
    const float *A, *B, *bias;
    float *C;
    int ldb, N, K;
    long long aO, bO, cO, biasO;
};

// ----------------------------- fp16 cp.async GEMM (persistent, 4-stage) ----
// R14 configuration: K-slice 32, 4 stages, 92 KB smem, 2 CTAs/SM.
template<int BN>
__global__ __launch_bounds__(256, 2) void mma_k(GPH p) {
    constexpr int WGN  = (BN == 128) ? 4 : 2;
    constexpr int WGM  = 8 / WGN;
    constexpr int WM   = 128 / WGM;
    constexpr int WN   = BN / WGN;
    constexpr int MF   = WM / 16;
    constexpr int NF   = WN / 8;
    constexpr int ASTH = 56;
    constexpr int BSTH = BN + 8;
    constexpr int AW   = 128 * ASTH / 2;
    constexpr int BW   = 32 * BSTH / 2;

    extern __shared__ unsigned smw[];
    unsigned sb = (unsigned)__cvta_generic_to_shared(smw);
    unsigned aBase[4], bBase[4];
    #pragma unroll
    for (int s = 0; s < 4; s++) {
        aBase[s] = sb + (unsigned)(s * AW) * 4u;
        bBase[s] = sb + (unsigned)(4 * AW + s * BW) * 4u;
    }

    int tid = threadIdx.x, lane = tid & 31, warp = tid >> 5;
    int wm = warp / WGN, wn = warp % WGN;
    int ar0 = tid >> 2, ac = (tid & 3) * 8;
    int aRow = (lane & 7) + ((lane >> 3) & 1) * 8;
    unsigned aKoff = ((lane >> 4) & 1) * 16;
    int bRowT = (lane & 7) + ((lane >> 3) & 1) * 8;
    int bColT = ((lane >> 4) & 1) * 8;

    for (int t = blockIdx.x; t < p.tiles; t += gridDim.x) {
        int bx = t % p.gx; int rr = t / p.gx;
        int by = rr % p.gy; int bz = rr / p.gy;

        __syncthreads();

        const __half *A, *B;
        float *C = nullptr; __half *Ch = nullptr;
        const float *bias = nullptr, *res = nullptr;
        if (p.hmode) {
            A = p.A + (((bz >> 1) & 1) ? p.aI : 0);
            B = p.B + (size_t)bz * p.bO;
            if (p.C)  C  = p.C  + (size_t)bz * p.cO;
            if (p.Ch) Ch = p.Ch + (size_t)bz * p.cO;
        } else {
            int zo = bz / p.zDiv, zi = bz % p.zDiv;
            A = p.A + zo * p.aO + zi * p.aI;
            B = p.B + zo * p.bO + zi * p.bI;
            if (p.C)  C  = p.C  + zo * p.cO + zi * p.cI;
            if (p.Ch) Ch = p.Ch + zo * p.cO + zi * p.cI;
            if (p.bias) bias = p.bias + zo * p.biasO;
            if (p.res)  res  = p.res + zo * p.rO + zi * p.rI;
        }
        int m0 = bx * 128, n0 = by * BN;
        bool av0 = (m0 + ar0) < p.M, av1 = (m0 + ar0 + 64) < p.M;

        auto issue = [&](int s, int k0) {
            cpa16(aBase[s] + (unsigned)(ar0 * ASTH + ac) * 2u,
                  A + (size_t)(m0 + ar0) * p.lda + k0 + ac, av0);
            cpa16(aBase[s] + (unsigned)((ar0 + 64) * ASTH + ac) * 2u,
                  A + (size_t)(m0 + ar0 + 64) * p.lda + k0 + ac, av1);
            if (BN == 128) {
                int br = tid >> 4, bc = (tid & 15) * 8;
                cpa16(bBase[s] + (unsigned)(br * BSTH + bc) * 2u,
                      B + (size_t)(k0 + br) * p.ldb + n0 + bc, true);
                cpa16(bBase[s] + (unsigned)((br + 16) * BSTH + bc) * 2u,
                      B + (size_t)(k0 + br + 16) * p.ldb + n0 + bc, true);
            } else {
                int br = tid >> 3, bc = (tid & 7) * 8;
                cpa16(bBase[s] + (unsigned)(br * BSTH + bc) * 2u,
                      B + (size_t)(k0 + br) * p.ldb + n0 + bc, true);
            }
        };

        float acc[MF][NF][4];
        #pragma unroll
        for (int f = 0; f < MF; f++)
            #pragma unroll
            for (int j = 0; j < NF; j++)
                #pragma unroll
                for (int q = 0; q < 4; q++) acc[f][j][q] = 0.f;

        int nIter = p.K >> 5;
        issue(0, 0);  CP_COMMIT;
        issue(1, 32); CP_COMMIT;
        issue(2, 64); CP_COMMIT;

        for (int i = 0; i < nIter; i++) {
            CP_WAIT2;
            __syncthreads();
            if (i + 3 < nIter) issue((i + 3) & 3, (i + 3) * 32);
            CP_COMMIT;

            int s = i & 3;
            unsigned aB = aBase[s], bB = bBase[s];
            #pragma unroll
            for (int kk = 0; kk < 32; kk += 16) {
                unsigned bfr[NF][2];
                #pragma unroll
                for (int j = 0; j < NF; j += 2) {
                    unsigned addr = bB + (unsigned)((kk + bRowT) * BSTH
                                  + wn * WN + j * 8 + bColT) * 2u;
                    ldsm4t(bfr[j][0], bfr[j][1], bfr[j+1][0], bfr[j+1][1], addr);
                }
                #pragma unroll
                for (int f = 0; f < MF; f++) {
                    int row = wm * WM + f * 16 + aRow;
                    unsigned addr = aB + (unsigned)(row * ASTH + kk) * 2u + aKoff;
                    unsigned afr[4];
                    ldsm4(afr[0], afr[1], afr[2], afr[3], addr);
                    #pragma unroll
                    for (int j = 0; j < NF; j++) mma16(acc[f][j], afr, bfr[j]);
                }
            }
        }

        #pragma unroll
        for (int f = 0; f < MF; f++) {
            int r0 = m0 + wm * WM + f * 16 + (lane >> 2);
            int r1 = r0 + 8;
            #pragma unroll
            for (int j = 0; j < NF; j++) {
                int col = n0 + wn * WN + j * 8 + 2 * (lane & 3);
                float b0 = 0.f, b1 = 0.f;
                if (bias) { b0 = bias[col]; b1 = bias[col + 1]; }
                float v0 = acc[f][j][0] + b0, v1 = acc[f][j][1] + b1;
                float v2 = acc[f][j][2] + b0, v3 = acc[f][j][3] + b1;
                if (p.relu) {
                    v0 = fmaxf(v0, 0.f); v1 = fmaxf(v1, 0.f);
                    v2 = fmaxf(v2, 0.f); v3 = fmaxf(v3, 0.f);
                }
                if (r0 < p.M) {
                    if (res) {
                        v0 += p.resScale * res[(size_t)r0 * p.ldres + col];
                        v1 += p.resScale * res[(size_t)r0 * p.ldres + col + 1];
                    }
                    if (C)  *(float2*)&C[(size_t)r0 * p.ldc + col] = make_float2(v0, v1);
                    if (Ch) *(unsigned*)&Ch[(size_t)r0 * p.ldc + col] = h2u(v0, v1);
                }
                if (r1 < p.M) {
                    if (res) {
                        v2 += p.resScale * res[(size_t)r1 * p.ldres + col];
                        v3 += p.resScale * res[(size_t)r1 * p.ldres + col + 1];
                    }
                    if (C)  *(float2*)&C[(size_t)r1 * p.ldc + col] = make_float2(v2, v3);
                    if (Ch) *(unsigned*)&Ch[(size_t)r1 * p.ldc + col] = h2u(v2, v3);
                }
            }
        }
    }
}

#define MMA_SMEM(BN) ((4 * (128*56/2) + 4 * (32*((BN)+8)/2)) * 4)
#define PERSIST_CTAS 296

static void mgemm(const __half* A, int lda, const __half* B, int ldb,
                  float* C, __half* Ch, int ldc,
                  int M, int N, int K,
                  const float* bias = nullptr, const float* res = nullptr, int ldres = 0,
                  float resScale = 0.f, int relu = 0,
                  int z = 1, int zDiv = 1,
                  long long aO=0, long long aI=0, long long bO=0, long long bI=0,
                  long long cO=0, long long cI=0, long long rO=0, long long rI=0,
                  long long biasO=0, int hmode = 0) {
    GPH p;
    p.A=A; p.B=B; p.bias=bias; p.res=res; p.C=C; p.Ch=Ch;
    p.lda=lda; p.ldb=ldb; p.ldc=ldc; p.ldres=ldres;
    p.M=M; p.N=N; p.K=K; p.resScale=resScale; p.relu=relu; p.zDiv=zDiv; p.hmode=hmode;
    p.aO=aO; p.aI=aI; p.bO=bO; p.bI=bI; p.cO=cO; p.cI=cI; p.rO=rO; p.rI=rI; p.biasO=biasO;
    p.gx = (M + 127) / 128;
    if (N % 128 == 0) {
        p.gy = N / 128;
        p.tiles = p.gx * p.gy * z;
        int ctas = p.tiles < PERSIST_CTAS ? p.tiles : PERSIST_CTAS;
        mma_k<128><<<ctas, 256, MMA_SMEM(128)>>>(p);
    } else {
        p.gy = N / 64;
        p.tiles = p.gx * p.gy * z;
        int ctas = p.tiles < PERSIST_CTAS ? p.tiles : PERSIST_CTAS;
        mma_k<64><<<ctas, 256, MMA_SMEM(64)>>>(p);
    }
}

// ----------------------------- fused weight f32->f16 (9 segments) ----------
struct TOH9 {
    const float* s[9];
    __half* d[9];
    int off[10];
};
__global__ void k_tohalf_all(TOH9 t) {
    int g = blockIdx.x * blockDim.x + threadIdx.x;
    if (g >= t.off[9]) return;
    int seg = 0;
    #pragma unroll
    for (int i = 1; i < 9; i++) seg += (g >= t.off[i]);
    int loc = (g - t.off[seg]) * 8;
    const float* in = t.s[seg] + loc;
    __half* out = t.d[seg] + loc;
    uint2 a = f4h(*(const float4*)(in));
    uint2 b = f4h(*(const float4*)(in + 4));
    *(uint4*)(out) = make_uint4(a.x, a.y, b.x, b.y);
}

// ----------------------------- flash attention (fp16, cp.async) ------------
#define KSTW 36
#define FLASH_SMEM ((4*64*KSTW + 128*KSTW) * 4)

__global__ __launch_bounds__(256, 2) void k_flash() {
    extern __shared__ unsigned sm[];
    unsigned sb = (unsigned)__cvta_generic_to_shared(sm);
    unsigned kOff[2] = { sb, sb + 4608u*4u };
    unsigned vOff[2] = { sb + 2304u*4u, sb + 6912u*4u };
    unsigned* sP = sm + 9216;
    unsigned sPb = sb + 9216u*4u;

    int tid = threadIdx.x, lane = tid & 31, w = tid >> 5;
    int m0 = blockIdx.x * 128;
    int bh = blockIdx.y; int h = bh & 7, b = bh >> 3;
    const __half* qb = g_qkvh + (size_t)(b * LL) * QKVD + h * 192;

    int l15 = lane & 15;
    int aRow = (lane & 7) + ((lane >> 3) & 1) * 8;
    unsigned aKoff = ((lane >> 4) & 1) * 16;
    int arow = 16*w + aRow;

    int key = tid >> 2, kc4 = tid & 3;
    auto issue = [&](int st, int kt) {
        const __half* kp = qb + (size_t)(kt*64 + key) * QKVD + 64;
        unsigned kd = kOff[st] + (unsigned)key * 144u;
        cpa16(kd + kc4*16,      kp + kc4*8,       true);
        cpa16(kd + (kc4+4)*16,  kp + (kc4+4)*8,   true);
        unsigned vd = vOff[st] + (unsigned)key * 144u;
        cpa16(vd + kc4*16,      kp + 64 + kc4*8,  true);
        cpa16(vd + (kc4+4)*16,  kp + 64 + (kc4+4)*8, true);
    };

    issue(0, 0); CP_COMMIT;

    {
        int row = tid >> 1, dh = (tid & 1) * 32;
        const uint4* src = (const uint4*)(qb + (size_t)(m0 + row) * QKVD + dh);
        unsigned* dst = sP + row * KSTW + dh/2;
        #pragma unroll
        for (int c = 0; c < 4; c++) *(uint4*)(dst + c*4) = src[c];
    }
    __syncthreads();
    unsigned qf[4][4];
    #pragma unroll
    for (int kc = 0; kc < 4; kc++)
        ldsm4(qf[kc][0], qf[kc][1], qf[kc][2], qf[kc][3],
              sPb + (unsigned)(arow * KSTW) * 4u + (unsigned)kc * 32u + aKoff);

    float accO[8][4];
    #pragma unroll
    for (int j = 0; j < 8; j++)
        #pragma unroll
        for (int q = 0; q < 4; q++) accO[j][q] = 0.f;
    float m0r = -INFINITY, m1r = -INFINITY, l0r = 0.f, l1r = 0.f;

    const unsigned* pmr0 = g_pm + ((size_t)bh * LL + m0 + 16*w + (lane >> 2)) * 16;
    const unsigned* pmr1 = pmr0 + 8 * 16;

    for (int kt = 0; kt < 8; kt++) {
        CP_WAIT0;
        __syncthreads();
        if (kt + 1 < 8) { issue((kt + 1) & 1, kt + 1); CP_COMMIT; }
        int st = kt & 1;

        float S[8][4];
        #pragma unroll
        for (int nt = 0; nt < 8; nt++)
            #pragma unroll
            for (int q = 0; q < 4; q++) S[nt][q] = 0.f;
        #pragma unroll
        for (int kc = 0; kc < 4; kc++) {
            #pragma unroll
            for (int nt = 0; nt < 8; nt++) {
                unsigned bb[2];
                unsigned addr = kOff[st] + (unsigned)((nt*8 + (l15 & 7)) * KSTW) * 4u
                                        + (unsigned)kc * 32u + (unsigned)(l15 >> 3) * 16u;
                ldsm2(bb[0], bb[1], addr);
                mma16(S[nt], qf[kc], bb);
            }
        }

        uint2 mw0 = *(const uint2*)(pmr0 + kt*2);
        uint2 mw1 = *(const uint2*)(pmr1 + kt*2);
        unsigned q0[2] = {mw0.x, mw0.y};
        unsigned q1[2] = {mw1.x, mw1.y};
        float rm0 = -INFINITY, rm1 = -INFINITY;
        #pragma unroll
        for (int nt = 0; nt < 8; nt++) {
            int j0 = nt*8 + 2*(lane & 3), j1 = j0 + 1;
            S[nt][0] = ((q0[j0>>5] >> (j0&31)) & 1u) ? S[nt][0]*0.125f : -INFINITY;
            S[nt][1] = ((q0[j1>>5] >> (j1&31)) & 1u) ? S[nt][1]*0.125f : -INFINITY;
            S[nt][2] = ((q1[j0>>5] >> (j0&31)) & 1u) ? S[nt][2]*0.125f : -INFINITY;
            S[nt][3] = ((q1[j1>>5] >> (j1&31)) & 1u) ? S[nt][3]*0.125f : -INFINITY;
            rm0 = fmaxf(rm0, fmaxf(S[nt][0], S[nt][1]));
            rm1 = fmaxf(rm1, fmaxf(S[nt][2], S[nt][3]));
        }
        rm0 = fmaxf(rm0, __shfl_xor_sync(0xffffffffu, rm0, 1));
        rm0 = fmaxf(rm0, __shfl_xor_sync(0xffffffffu, rm0, 2));
        rm1 = fmaxf(rm1, __shfl_xor_sync(0xffffffffu, rm1, 1));
        rm1 = fmaxf(rm1, __shfl_xor_sync(0xffffffffu, rm1, 2));

        float mn0 = fmaxf(m0r, rm0), mn1 = fmaxf(m1r, rm1);
        float a0 = __expf(m0r - mn0), a1 = __expf(m1r - mn1);
        m0r = mn0; m1r = mn1;

        int prow0 = 16*w + (lane >> 2), prow1 = prow0 + 8;
        float rs0 = 0.f, rs1 = 0.f;
        #pragma unroll
        for (int nt = 0; nt < 8; nt++) {
            int jw = nt*4 + (lane & 3);
            float p00 = __expf(S[nt][0] - mn0), p01 = __expf(S[nt][1] - mn0);
            float p10 = __expf(S[nt][2] - mn1), p11 = __expf(S[nt][3] - mn1);
            rs0 += p00 + p01; rs1 += p10 + p11;
            sP[prow0*KSTW + jw] = h2u(p00, p01);
            sP[prow1*KSTW + jw] = h2u(p10, p11);
        }
        rs0 += __shfl_xor_sync(0xffffffffu, rs0, 1);
        rs0 += __shfl_xor_sync(0xffffffffu, rs0, 2);
        rs1 += __shfl_xor_sync(0xffffffffu, rs1, 1);
        rs1 += __shfl_xor_sync(0xffffffffu, rs1, 2);
        l0r = l0r * a0 + rs0;
        l1r = l1r * a1 + rs1;

        #pragma unroll
        for (int j = 0; j < 8; j++) {
            accO[j][0] *= a0; accO[j][1] *= a0;
            accO[j][2] *= a1; accO[j][3] *= a1;
        }
        __syncwarp();

        #pragma unroll
        for (int kc = 0; kc < 4; kc++) {
            unsigned pf[4];
            ldsm4(pf[0], pf[1], pf[2], pf[3],
                  sPb + (unsigned)(arow * KSTW) * 4u + (unsigned)kc * 32u + aKoff);
            #pragma unroll
            for (int nt = 0; nt < 8; nt++) {
                unsigned bb[2];
                unsigned addr = vOff[st] + (unsigned)((kc*16 + (l15 & 7) + (l15 >> 3)*8) * KSTW) * 4u
                                        + (unsigned)nt * 16u;
                ldsm2t(bb[0], bb[1], addr);
                mma16(accO[nt], pf, bb);
            }
        }
    }

    float inv0 = 1.f / l0r, inv1 = 1.f / l1r;
    int r0 = m0 + 16*w + (lane >> 2), r1 = r0 + 8;
    __half* o0 = g_oh + (size_t)(b*LL + r0) * NHID + h*64;
    __half* o1 = g_oh + (size_t)(b*LL + r1) * NHID + h*64;
    #pragma unroll
    for (int nt = 0; nt < 8; nt++) {
        int col = nt*8 + 2*(lane & 3);
        *(unsigned*)&o0[col] = h2u(accO[nt][0]*inv0, accO[nt][1]*inv0);
        *(unsigned*)&o1[col] = h2u(accO[nt][2]*inv1, accO[nt][3]*inv1);
    }
}

// pack mask (int32 bool, layout [b][i][h][j]) -> bits [b][h][i][j/32]
__global__ void k_packmask(const int* __restrict__ mask) {
    int row = blockIdx.x * 8 + (threadIdx.x >> 5);
    int lane = threadIdx.x & 31;
    const int* mr = mask + (size_t)row * LL;
    int b_i = row >> 3, h = row & 7;
    int b = b_i >> 9, i = b_i & 511;
    unsigned* out = g_pm + (((size_t)(b*HEADS + h) * LL + i) << 4);
    #pragma unroll
    for (int wd = 0; wd < 16; wd++) {
        unsigned bits = __ballot_sync(0xffffffffu, mr[wd*32 + lane] != 0);
        if (lane == 0) out[wd] = bits;
    }
}

// ----------------------------- small FFMA GEMM (M=1) -----------------------
__global__ void gemm1_k(GP p) {
    int zo = blockIdx.z;
    const float* A = p.A + zo * p.aO;
    const float* B = p.B + zo * p.bO;
    float* C = p.C + zo * p.cO;
    const float* bias = p.bias ? p.bias + zo * p.biasO : nullptr;
    int n = blockIdx.x * 64 + threadIdx.x;
    if (n >= p.N) return;
    float s = 0.f;
    for (int k = 0; k < p.K; k++) s += A[k] * B[(size_t)k * p.ldb + n];
    if (bias) s += bias[n];
    C[n] = s;
}

// ----------------------------- small kernels -------------------------------
__global__ void k_embed(const float* __restrict__ emb, const float* __restrict__ pos,
                        const int* __restrict__ idxs) {
    int tok = blockIdx.x;
    int b = tok >> 9, s = tok & 511;
    int id = (s == 0) ? 0 : idxs[b*SS + s - 1];
    const float4* e  = (const float4*)(emb + (size_t)id * NHID);
    const float4* pr = (const float4*)(pos + (size_t)s  * NHID);
    float4* hr = (float4*)(g_h + (size_t)tok * NHID);
    uint2*  hh = (uint2*)(g_hh + (size_t)tok * NHID);
    int t = threadIdx.x;
    float4 a = e[t], c = pr[t];
    float4 v = make_float4(a.x+c.x, a.y+c.y, a.z+c.z, a.w+c.w);
    hr[t] = v;
    hh[t] = f4h(v);
}

__global__ void k_ln_add(float* __restrict__ out, const float* __restrict__ inp,
                         const float* __restrict__ base, int hgMap,
                         const float* __restrict__ gw, const float* __restrict__ bw,
                         __half* __restrict__ outH, int zg) {
    int n = blockIdx.x;
    int t = threadIdx.x;
    if (zg && n >= NNODE) {                 // fused zg tail: copy h[b][0] rows
        int b = n - NNODE;
        #pragma unroll
        for (int i = 0; i < 4; i++) {
            int c = t + i*128;
            out[(size_t)NNODE*NHID + b*NHID + c] = g_h[((size_t)b*LL) * NHID + c];
        }
        return;
    }
    const float* xr = inp + (size_t)n * NHID;
    size_t brow;
    if (hgMap) { int b = n / SS, s = n % SS; brow = ((size_t)(b*LL + s + 1)) * NHID; }
    else brow = (size_t)n * NHID;
    float x[4];
    #pragma unroll
    for (int i = 0; i < 4; i++) x[i] = xr[t + i*128];
    __shared__ float red[128];
    red[t] = x[0]+x[1]+x[2]+x[3]; __syncthreads();
    for (int s = 64; s > 0; s >>= 1) { if (t < s) red[t] += red[t+s]; __syncthreads(); }
    float mu = red[0] * (1.f/512.f); __syncthreads();
    float d[4], vs = 0.f;
    #pragma unroll
    for (int i = 0; i < 4; i++) { d[i] = x[i] - mu; vs += d[i]*d[i]; }
    red[t] = vs; __syncthreads();
    for (int s = 64; s > 0; s >>= 1) { if (t < s) red[t] += red[t+s]; __syncthreads(); }
    float inv = rsqrtf(red[0] * (1.f/512.f) + 1e-5f);
    #pragma unroll
    for (int i = 0; i < 4; i++) {
        int c = t + i*128;
        float v = base[brow + c] + d[i]*inv*gw[c] + bw[c];
        out[(size_t)n*NHID + c] = v;
        if (outH) outH[(size_t)n*NHID + c] = __float2half_rn(v);
    }
}

__global__ void k_copyxf() {
    int n = blockIdx.x;
    int b = n / SS, s = n % SS;
    const float4* src = (const float4*)(g_h + ((size_t)(b*LL + s + 1)) * NHID);
    uint2* dst = (uint2*)(g_xfh + (size_t)n * NHID);
    dst[threadIdx.x] = f4h(src[threadIdx.x]);
}

__global__ void k_zero_ints() {
    int i = blockIdx.x*blockDim.x + threadIdx.x;
    if (i < 2*NNODE) { g_ind[i] = 0; g_outd[i] = 0; g_cur[i] = 0; }
}

__global__ void k_count2(const int* __restrict__ s0, const int* __restrict__ d0,
                         const int* __restrict__ s1, const int* __restrict__ d1) {
    int gi = blockIdx.y;
    const int* src = gi ? s1 : s0;
    const int* dst = gi ? d1 : d0;
    int e = blockIdx.x*blockDim.x + threadIdx.x;
    if (e < EE) {
        atomicAdd(&g_ind [gi*NNODE + dst[e]], 1);
        atomicAdd(&g_outd[gi*NNODE + src[e]], 1);
    }
}

__global__ void k_scan() {
    __shared__ int sh[1024];
    int gi = blockIdx.x;
    int t = threadIdx.x;
    int base = gi * NNODE;
    int loc[8]; int sum = 0;
    #pragma unroll
    for (int i = 0; i < 8; i++) {
        int idx = t*8 + i;
        int v = (idx < NNODE) ? g_ind[base + idx] : 0;
        loc[i] = sum; sum += v;
    }
    sh[t] = sum; __syncthreads();
    for (int d = 1; d < 1024; d <<= 1) {
        int v = (t >= d) ? sh[t-d] : 0; __syncthreads();
        sh[t] += v; __syncthreads();
    }
    int pre = (t > 0) ? sh[t-1] : 0;
    #pragma unroll
    for (int i = 0; i < 8; i++) {
        int idx = t*8 + i;
        if (idx < NNODE) g_off[base + idx] = pre + loc[i];
    }
}

__global__ void k_scatter2(const int* __restrict__ s0, const int* __restrict__ d0,
                           const int* __restrict__ s1, const int* __restrict__ d1) {
    int gi = blockIdx.y;
    const int* src = gi ? s1 : s0;
    const int* dst = gi ? d1 : d0;
    int e = blockIdx.x*blockDim.x + threadIdx.x;
    if (e < EE) {
        int d = dst[e];
        int p = g_off[gi*NNODE + d] + atomicAdd(&g_cur[gi*NNODE + d], 1);
        g_csr[gi*EE + p] = src[e];
    }
}

__global__ void k_scales() {
    int i = blockIdx.x*blockDim.x + threadIdx.x;
    if (i < 2*NNODE) {
        float in = (float)g_ind[i], od = (float)g_outd[i];
        g_sin [i] = rsqrtf(fmaxf(in, 1.f));
        g_sout[i] = rsqrtf(fmaxf(od, 1.f));
        g_inv1[i] = 1.f / (in + 1.f);
    }
}

__global__ void k_prop_sage(const __half* __restrict__ x, long long xper,
                            __half* __restrict__ out) {
    int gi = blockIdx.y;
    int wid = blockIdx.x * (blockDim.x >> 5) + (threadIdx.x >> 5);
    if (wid >= NNODE) return;
    int lane = threadIdx.x & 31;
    const __half* xb = x + (size_t)gi * xper;
    float a[16];
    #pragma unroll
    for (int i = 0; i < 16; i++) a[i] = 0.f;
    {
        const uint4* xr = (const uint4*)(xb + (size_t)wid * NHID);
        addh8(a, xr[lane], 1.f);
        addh8(a + 8, xr[lane + 32], 1.f);
    }
    int s = g_off[gi*NNODE + wid], e = s + g_ind[gi*NNODE + wid];
    const int* csr = g_csr + gi*EE;
    for (int j = s; j < e; j++) {
        const uint4* sr = (const uint4*)(xb + (size_t)csr[j] * NHID);
        addh8(a, sr[lane], 1.f);
        addh8(a + 8, sr[lane + 32], 1.f);
    }
    float sc = g_inv1[gi*NNODE + wid];
    uint4* o = (uint4*)(out + (size_t)gi * NNODE * NHID + (size_t)wid * NHID);
    o[lane]      = pack8(a, sc);
    o[lane + 32] = pack8(a + 8, sc);
}

__global__ void k_prop_gc(const __half* __restrict__ q, __half* __restrict__ outT) {
    int gi = blockIdx.y;
    int wid = blockIdx.x * (blockDim.x >> 5) + (threadIdx.x >> 5);
    if (wid >= NNODE) return;
    int lane = threadIdx.x & 31;
    const __half* qb = q + (size_t)gi * NNODE * NHID;
    float a[16];
    #pragma unroll
    for (int i = 0; i < 16; i++) a[i] = 0.f;
    float ts = 0.f;
    int s = g_off[gi*NNODE + wid], e = s + g_ind[gi*NNODE + wid];
    const int* csr = g_csr + gi*EE;
    for (int j = s; j < e; j++) {
        int sn = csr[j];
        float so = g_sout[gi*NNODE + sn];
        ts += so;
        const uint4* sr = (const uint4*)(qb + (size_t)sn * NHID);
        addh8(a, sr[lane], so);
        addh8(a + 8, sr[lane + 32], so);
    }
    uint4* o = (uint4*)(outT + (size_t)gi * NNODE * NHID + (size_t)wid * NHID);
    o[lane]      = pack8(a, 1.f);
    o[lane + 32] = pack8(a + 8, 1.f);
    if (lane == 0) g_tvec[gi*NNODE + wid] = ts;
}

__global__ void k_xcepi(const float* __restrict__ gc3b) {
    int n = blockIdx.x; int c = threadIdx.x;
    int g = c_pat[c >> 6];
    float si = g_sin[g*NNODE + n], tv = g_tvec[g*NNODE + n];
    size_t idx = (size_t)n*NHID + c;
    g_xc[idx] = si * g_xc[idx] + si * tv * g_dcat[c] + gc3b[c];
}

// ----------------------------- host orchestration --------------------------
#define SYMF(name, var) { void* _p; cudaGetSymbolAddress(&_p, name); var = (float*)_p; }
#define SYMH(name, var) { void* _p; cudaGetSymbolAddress(&_p, name); var = (__half*)_p; }

extern "C" void kernel_launch(void* const* d_in, const int* in_sizes, int n_in,
                              void* d_out, int out_size) {
    const float* in_embed  = (const float*)d_in[0];
    const float* pos_embed = (const float*)d_in[1];
    const float* qkv_w     = (const float*)d_in[2];
    const float* qkv_b     = (const float*)d_in[3];
    const float* attn_w    = (const float*)d_in[4];
    const float* attn_b    = (const float*)d_in[5];
    const float* ff1_w     = (const float*)d_in[6];
    const float* ff1_b     = (const float*)d_in[7];
    const float* ff2_w     = (const float*)d_in[8];
    const float* ff2_b     = (const float*)d_in[9];
    const float* sage1_w   = (const float*)d_in[10];
    const float* sage1_b   = (const float*)d_in[11];
    const float* sage2_w   = (const float*)d_in[12];
    const float* sage2_b   = (const float*)d_in[13];
    const float* gc3_w     = (const float*)d_in[14];
    const float* gc3_b     = (const float*)d_in[15];
    const float* gff1_w    = (const float*)d_in[16];
    const float* gff1_b    = (const float*)d_in[17];
    const float* gff2_w    = (const float*)d_in[18];
    const float* gff2_b    = (const float*)d_in[19];
    const float* ln_g      = (const float*)d_in[20];
    const float* ln_b      = (const float*)d_in[21];
    const int*   in_idxs   = (const int*)d_in[22];
    const int*   mask      = (const int*)d_in[23];   // bool marshalled as int32
    const int*   gt_src    = (const int*)d_in[24];
    const int*   gt_dst    = (const int*)d_in[25];
    const int*   at_src    = (const int*)d_in[26];
    const int*   at_dst    = (const int*)d_in[27];

    float *h, *x, *xc, *xg, *cc, *dc;
    SYMF(g_h, h); SYMF(g_x, x); SYMF(g_xc, xc); SYMF(g_xg, xg);
    SYMF(g_ccat, cc); SYMF(g_dcat, dc);
    __half *hh, *qkvh, *oh, *xh, *ffh, *xfh, *Ph, *Qh, *Th, *Mh, *Nch, *xgh, *fgh;
    __half *qkvwh, *attnwh, *ff1wh, *ff2wh, *s1wh, *s2wh, *gc3wh, *gff1wh, *gff2wh;
    SYMH(g_hh, hh); SYMH(g_qkvh, qkvh); SYMH(g_oh, oh); SYMH(g_xh, xh); SYMH(g_ffh, ffh);
    SYMH(g_xfh, xfh); SYMH(g_Ph, Ph); SYMH(g_Qh, Qh); SYMH(g_Th, Th);
    SYMH(g_Mh, Mh); SYMH(g_Nch, Nch); SYMH(g_xgh, xgh); SYMH(g_fgh, fgh);
    SYMH(g_qkvwh, qkvwh); SYMH(g_attnwh, attnwh); SYMH(g_ff1wh, ff1wh);
    SYMH(g_ff2wh, ff2wh); SYMH(g_s1wh, s1wh); SYMH(g_s2wh, s2wh);
    SYMH(g_gc3wh, gc3wh); SYMH(g_gff1wh, gff1wh); SYMH(g_gff2wh, gff2wh);

    static int smemSet = 0;
    if (!smemSet) {
        cudaFuncSetAttribute(k_flash, cudaFuncAttributeMaxDynamicSharedMemorySize, FLASH_SMEM);
        cudaFuncSetAttribute(mma_k<128>, cudaFuncAttributeMaxDynamicSharedMemorySize, MMA_SMEM(128));
        cudaFuncSetAttribute(mma_k<64>,  cudaFuncAttributeMaxDynamicSharedMemorySize, MMA_SMEM(64));
        smemSet = 1;
    }

    // ---- fused weight f32 -> f16 (single launch) ----
    {
        TOH9 t;
        const float* srcs[9] = {qkv_w, attn_w, ff1_w, ff2_w, sage1_w, sage2_w,
                                gc3_w, gff1_w, gff2_w};
        __half* dsts[9] = {qkvwh, attnwh, ff1wh, ff2wh, s1wh, s2wh,
                           gc3wh, gff1wh, gff2wh};
        int ns[9] = {4*NHID*QKVD, 4*NHID*NHID, 4*NHID*FFD, 4*FFD*NHID,
                     HEADS*NHID*NHID, HEADS*NHID*NHID, HEADS*NHID*64,
                     NHID*NHID, NHID*NHID};
        int acc = 0;
        for (int i = 0; i < 9; i++) { t.s[i] = srcs[i]; t.d[i] = dsts[i];
                                      t.off[i] = acc; acc += ns[i] / 8; }
        t.off[9] = acc;
        k_tohalf_all<<<(acc + 255)/256, 256>>>(t);
    }

    // ---- embedding + mask packing ----
    k_embed<<<NTOK, 128>>>(in_embed, pos_embed, in_idxs);
    k_packmask<<<BB*LL*HEADS/8, 256>>>(mask);

    // ---- transformer layers ----
    for (int l = 0; l < 4; l++) {
        mgemm(hh, NHID, qkvwh + (size_t)l*NHID*QKVD, QKVD, nullptr, qkvh, QKVD,
              NTOK, QKVD, NHID, qkv_b + l*QKVD);
        k_flash<<<dim3(LL/128, BB*HEADS), 256, FLASH_SMEM>>>();
        mgemm(oh, NHID, attnwh + (size_t)l*NHID*NHID, NHID, x, xh, NHID,
              NTOK, NHID, NHID, attn_b + l*NHID, h, NHID, 2.0f);
        mgemm(xh, NHID, ff1wh + (size_t)l*NHID*FFD, FFD, nullptr, ffh, FFD,
              NTOK, FFD, NHID, ff1_b + l*FFD, nullptr, 0, 0.f, /*relu=*/1);
        mgemm(ffh, FFD, ff2wh + (size_t)l*FFD*NHID, NHID, h, hh, NHID,
              NTOK, NHID, FFD, ff2_b + l*NHID, x, NHID, 1.0f);
    }

    // ---- graph preprocessing (merged launches) ----
    k_zero_ints<<<(2*NNODE + 255)/256, 256>>>();
    k_count2<<<dim3(EE/256, 2), 256>>>(gt_src, gt_dst, at_src, at_dst);
    k_scan<<<2, 1024>>>();
    k_scatter2<<<dim3(EE/256, 2), 256>>>(gt_src, gt_dst, at_src, at_dst);
    k_scales<<<(2*NNODE + 255)/256, 256>>>();
    k_copyxf<<<NNODE, 128>>>();

    // ---- propagations: both graphs per launch, fp16 data ----
    int propBlocks = (NNODE + 7) / 8;
    k_prop_sage<<<dim3(propBlocks, 2), 256>>>(xfh, 0, Ph);
    k_prop_sage<<<dim3(propBlocks, 2), 256>>>(Ph, (long long)NNODE*NHID, Qh);
    k_prop_gc  <<<dim3(propBlocks, 2), 256>>>(Qh, Th);

    // ---- collapse per-head weights ----
    mgemm(s1wh, NHID, s2wh, NHID, nullptr, Mh, NHID, NHID, NHID, NHID,
          nullptr, nullptr, 0, 0.f, 0, HEADS, 1,
          (long long)NHID*NHID, 0, (long long)NHID*NHID, 0, (long long)NHID*NHID, 0);
    mgemm(Mh, NHID, gc3wh, 64, nullptr, Nch, 64, NHID, 64, NHID,
          nullptr, nullptr, 0, 0.f, 0, HEADS, 1,
          (long long)NHID*NHID, 0, (long long)NHID*64, 0, (long long)NHID*64, 0);
    {
        GP p; p.A=sage1_b; p.B=sage2_w; p.bias=sage2_b; p.C=cc;
        p.ldb=NHID; p.N=NHID; p.K=NHID;
        p.aO=NHID; p.bO=(long long)NHID*NHID; p.cO=NHID; p.biasO=NHID;
        gemm1_k<<<dim3((NHID+63)/64,1,HEADS), 64>>>(p);
    }
    {
        GP p; p.A=cc; p.B=gc3_w; p.bias=nullptr; p.C=dc;
        p.ldb=64; p.N=64; p.K=NHID;
        p.aO=NHID; p.bO=(long long)NHID*64; p.cO=64; p.biasO=0;
        gemm1_k<<<dim3(1,1,HEADS), 64>>>(p);
    }

    // ---- xc per head: A = Th[(z>>1)&1] via hmode ----
    mgemm(Th, NHID, Nch, 64, xc, nullptr, NHID,
          NNODE, 64, NHID, nullptr, nullptr, 0, 0.f, 0,
          HEADS, 1,
          0, (long long)NNODE*NHID,
          (long long)NHID*64, 0,
          64, 0, 0, 0, 0, /*hmode=*/1);
    k_xcepi<<<NNODE, 512>>>(gc3_b);

    // ---- final: xg = hg + LN(xc); ff path; zbar = xg + LN(ff); fused zg ----
    k_ln_add<<<NNODE, 128>>>(xg, xc, h, /*hgMap=*/1, ln_g, ln_b, xgh, 0);
    mgemm(xgh, NHID, gff1wh, NHID, nullptr, fgh, NHID,
          NNODE, NHID, NHID, gff1_b, nullptr, 0, 0.f, /*relu=*/1);
    mgemm(fgh, NHID, gff2wh, NHID, xc, nullptr, NHID,
          NNODE, NHID, NHID, gff2_b);
    int zgTail = (out_size >= NNODE*NHID + BB*NHID) ? 1 : 0;
    k_ln_add<<<NNODE + (zgTail ? BB : 0), 128>>>((float*)d_out, xc, xg,
          /*hgMap=*/0, ln_g, ln_b, nullptr, zgTail);
}